// round 8
// baseline (speedup 1.0000x reference)
#include <cuda_runtime.h>
#include <cuda_bf16.h>
#include <cstdint>

#define BS       8
#define CCH      32
#define TLEN     2048
#define PATCH_N  16
#define DM       512
#define NHEADS   8
#define HD       64
#define DFF      2048
#define NLAYERS  3
#define BSEQ     (BS * CCH)       // 256
#define LTOT     240
#define MROWS    (BSEQ * LTOT)    // 61440

typedef __nv_bfloat16 bf16;

// ---------------- scratch ----------------
__device__ float g_h [MROWS * DM];
__device__ float g_q [MROWS * DM];
__device__ float g_k [MROWS * DM];
__device__ float g_v [MROWS * DM];
__device__ bf16  g_hhi[MROWS * DM], g_hlo[MROWS * DM];
__device__ bf16  g_thi[MROWS * DM], g_tlo[MROWS * DM];
__device__ bf16  g_fhi[(size_t)MROWS * DFF], g_flo[(size_t)MROWS * DFF];
#define WTOT 9437184
__device__ bf16  g_whi[WTOT], g_wlo[WTOT];

// ---------------- helpers ----------------
__device__ __forceinline__ uint32_t smem_u32(const void* p) {
    uint32_t a;
    asm("{ .reg .u64 t; cvta.to.shared.u64 t, %1; cvt.u32.u64 %0, t; }"
        : "=r"(a) : "l"(p));
    return a;
}
__device__ __forceinline__ void cpasync16(uint32_t d, const void* s) {
    asm volatile("cp.async.cg.shared.global [%0], [%1], 16;"
                 :: "r"(d), "l"(s) : "memory");
}
__device__ __forceinline__ float gelu_tanh(float x) {
    float x3 = x * x * x;
    float t = tanhf(0.7978845608028654f * (x + 0.044715f * x3));
    return 0.5f * x * (1.0f + t);
}
__device__ __forceinline__ uint32_t pack2bf(float x, float y) {
    __nv_bfloat162 h = __floats2bfloat162_rn(x, y);
    return *reinterpret_cast<uint32_t*>(&h);
}
__device__ __forceinline__ float bfhi(float x) {
    return __bfloat162float(__float2bfloat16(x));
}

#define LDSM_X4(r0, r1, r2, r3, addr) \
    asm volatile("ldmatrix.sync.aligned.m8n8.x4.shared.b16 {%0,%1,%2,%3}, [%4];" \
                 : "=r"(r0), "=r"(r1), "=r"(r2), "=r"(r3) : "r"(addr))

#define LDSM_X4_T(r0, r1, r2, r3, addr) \
    asm volatile("ldmatrix.sync.aligned.m8n8.x4.trans.shared.b16 {%0,%1,%2,%3}, [%4];" \
                 : "=r"(r0), "=r"(r1), "=r"(r2), "=r"(r3) : "r"(addr))

#define MMA_BF16(d, a, b0v, b1v) \
    asm volatile("mma.sync.aligned.m16n8k16.row.col.f32.bf16.bf16.f32 " \
                 "{%0,%1,%2,%3}, {%4,%5,%6,%7}, {%8,%9}, {%0,%1,%2,%3};" \
                 : "+f"((d)[0]), "+f"((d)[1]), "+f"((d)[2]), "+f"((d)[3]) \
                 : "r"((a)[0]), "r"((a)[1]), "r"((a)[2]), "r"((a)[3]), \
                   "r"(b0v), "r"(b1v))

// ---------------- weight split ----------------
__global__ void wsplit_kernel(const float* __restrict__ w,
                              bf16* __restrict__ hi, bf16* __restrict__ lo, int n4)
{
    int i = blockIdx.x * 256 + threadIdx.x;
    if (i >= n4) return;
    float4 v = ((const float4*)w)[i];
    float hx = bfhi(v.x), hy = bfhi(v.y), hz = bfhi(v.z), hw = bfhi(v.w);
    ((uint2*)hi)[i] = make_uint2(pack2bf(hx, hy), pack2bf(hz, hw));
    ((uint2*)lo)[i] = make_uint2(pack2bf(v.x - hx, v.y - hy), pack2bf(v.z - hz, v.w - hw));
}

// ---------------- embedding ----------------
__global__ void embed_kernel(const float* __restrict__ x_enc,
                             const float* __restrict__ Wemb,
                             float* __restrict__ h,
                             bf16* __restrict__ hhi, bf16* __restrict__ hlo)
{
    int tok = blockIdx.x;
    int r   = blockIdx.y;
    int tid = threadIdx.x;
    int b  = r >> 5;
    int cc = r & 31;

    int kstr, j;
    if (tok < 16)       { kstr = 8; j = tok; }
    else if (tok < 48)  { kstr = 4; j = tok - 16; }
    else if (tok < 112) { kstr = 2; j = tok - 48; }
    else                { kstr = 1; j = tok - 112; }

    __shared__ float xv[PATCH_N];
    if (tid < PATCH_N) {
        int tt = kstr * (j * PATCH_N + tid);
        xv[tid] = x_enc[((size_t)b * TLEN + tt) * CCH + cc];
    }
    __syncthreads();

    float pepos = (float)(j * kstr);
    const float cln = 9.210340371976184f / (float)DM;

    for (int d = tid; d < DM; d += 256) {
        float acc = 0.0f;
        #pragma unroll
        for (int p = 0; p < PATCH_N; p++)
            acc += xv[p] * Wemb[p * DM + d];
        int i2 = d & ~1;
        float ang = pepos * __expf(-(float)i2 * cln);
        float pv = (d & 1) ? cosf(ang) : sinf(ang);
        float val = acc + pv;
        size_t gi = ((size_t)r * LTOT + tok) * DM + d;
        h[gi] = val;
        float hx = bfhi(val);
        hhi[gi] = __float2bfloat16(hx);
        hlo[gi] = __float2bfloat16(val - hx);
    }
}

// ---------------- mma.sync bf16x3 GEMM with cp.async pipeline ----------------
#define AST 40          // A smem stride (elems): 32 + 8 pad -> 80B
#define BST 136         // B smem stride (elems): 128 + 8 pad -> 272B
#define STAGE_AH 0
#define STAGE_AL 10240  // bytes
#define STAGE_BH 20480
#define STAGE_BL 29184
#define STAGEB   37888
#define GSMEM    (2 * STAGEB)   // 75776 bytes

__global__ __launch_bounds__(256, 1)
void gemm_mma(const bf16* __restrict__ Ahi, const bf16* __restrict__ Alo,
              const bf16* __restrict__ Bhi, const bf16* __restrict__ Blo,
              const float* __restrict__ bias,
              float* __restrict__ C, bf16* __restrict__ Chi, bf16* __restrict__ Clo,
              int M, int N, int K, int doGelu)
{
    extern __shared__ char dsm[];
    uint32_t dynb = smem_u32(dsm);

    int tid  = threadIdx.x;
    int wid  = tid >> 5;
    int lane = tid & 31;
    int wm = wid & 3;
    int wn = wid >> 2;
    int m0 = blockIdx.y * 128;
    int n0 = blockIdx.x * 128;

    float acc[2][8][4];
    #pragma unroll
    for (int i = 0; i < 2; i++)
        #pragma unroll
        for (int j = 0; j < 8; j++)
            #pragma unroll
            for (int c = 0; c < 4; c++) acc[i][j][c] = 0.0f;

    // per-lane ldmatrix offsets (bytes, relative to each tile base)
    uint32_t aoffL = ((uint32_t)((wm * 32 + (lane & 15)) * AST + (lane >> 4) * 8)) * 2;
    uint32_t boffL = ((uint32_t)(((lane & 7) + ((lane >> 3) & 1) * 8) * BST
                                 + wn * 64 + (lane >> 4) * 8)) * 2;

    // cp.async per-thread chunk coords
    int arow0 = tid >> 2, ach = (tid & 3) * 8;               // + i*64 rows
    int brow0 = tid >> 4, bch = (tid & 15) * 8;              // + i*16 rows

    int nslab = K >> 5;

    auto issue = [&](int j, int s) {
        uint32_t sb = dynb + (uint32_t)s * STAGEB;
        int k0 = j * 32;
        #pragma unroll
        for (int i = 0; i < 2; i++) {
            int r = arow0 + i * 64;
            uint32_t off = (uint32_t)(r * AST + ach) * 2;
            size_t gi = (size_t)(m0 + r) * K + k0 + ach;
            cpasync16(sb + STAGE_AH + off, Ahi + gi);
            cpasync16(sb + STAGE_AL + off, Alo + gi);
        }
        #pragma unroll
        for (int i = 0; i < 2; i++) {
            int r = brow0 + i * 16;
            uint32_t off = (uint32_t)(r * BST + bch) * 2;
            size_t gi = (size_t)(k0 + r) * N + n0 + bch;
            cpasync16(sb + STAGE_BH + off, Bhi + gi);
            cpasync16(sb + STAGE_BL + off, Blo + gi);
        }
        asm volatile("cp.async.commit_group;" ::: "memory");
    };

    issue(0, 0);
    for (int j = 0; j < nslab; j++) {
        if (j + 1 < nslab) {
            issue(j + 1, (j + 1) & 1);
            asm volatile("cp.async.wait_group 1;" ::: "memory");
        } else {
            asm volatile("cp.async.wait_group 0;" ::: "memory");
        }
        __syncthreads();

        uint32_t sb = dynb + (uint32_t)(j & 1) * STAGEB;
        uint32_t aH = sb + STAGE_AH, aL = sb + STAGE_AL;
        uint32_t bH = sb + STAGE_BH, bL = sb + STAGE_BL;

        #pragma unroll
        for (int ks = 0; ks < 2; ks++) {
            uint32_t kbA = (uint32_t)(ks * 16) * 2;
            uint32_t kbB = (uint32_t)(ks * 16 * BST) * 2;

            uint32_t ah[2][4], al[2][4];
            #pragma unroll
            for (int mf = 0; mf < 2; mf++) {
                uint32_t off = aoffL + (uint32_t)(mf * 16 * AST) * 2 + kbA;
                LDSM_X4(ah[mf][0], ah[mf][1], ah[mf][2], ah[mf][3], aH + off);
                LDSM_X4(al[mf][0], al[mf][1], al[mf][2], al[mf][3], aL + off);
            }
            uint32_t bh[16], bl[16];
            #pragma unroll
            for (int nb = 0; nb < 4; nb++) {
                uint32_t off = boffL + (uint32_t)(nb * 16) * 2 + kbB;
                LDSM_X4_T(bh[nb * 4 + 0], bh[nb * 4 + 1], bh[nb * 4 + 2], bh[nb * 4 + 3], bH + off);
                LDSM_X4_T(bl[nb * 4 + 0], bl[nb * 4 + 1], bl[nb * 4 + 2], bl[nb * 4 + 3], bL + off);
            }

            #pragma unroll
            for (int mf = 0; mf < 2; mf++)
                #pragma unroll
                for (int nf = 0; nf < 8; nf++) {
                    MMA_BF16(acc[mf][nf], ah[mf], bh[nf * 2], bh[nf * 2 + 1]);
                    MMA_BF16(acc[mf][nf], ah[mf], bl[nf * 2], bl[nf * 2 + 1]);
                    MMA_BF16(acc[mf][nf], al[mf], bh[nf * 2], bh[nf * 2 + 1]);
                }
        }
        __syncthreads();
    }

    // epilogue
    int rbase = m0 + wm * 32 + (lane >> 2);
    int cbase = n0 + wn * 64 + (lane & 3) * 2;
    #pragma unroll
    for (int mf = 0; mf < 2; mf++) {
        #pragma unroll
        for (int nf = 0; nf < 8; nf++) {
            int col = cbase + nf * 8;
            float b0v = bias[col], b1v = bias[col + 1];
            float v0 = acc[mf][nf][0] + b0v;
            float v1 = acc[mf][nf][1] + b1v;
            float v2 = acc[mf][nf][2] + b0v;
            float v3 = acc[mf][nf][3] + b1v;
            if (doGelu) {
                v0 = gelu_tanh(v0); v1 = gelu_tanh(v1);
                v2 = gelu_tanh(v2); v3 = gelu_tanh(v3);
            }
            int r0 = rbase + mf * 16;
            if (C) {
                *(float2*)(C + (size_t)r0 * N + col)       = make_float2(v0, v1);
                *(float2*)(C + (size_t)(r0 + 8) * N + col) = make_float2(v2, v3);
            }
            if (Chi) {
                float h0 = bfhi(v0), h1 = bfhi(v1), h2 = bfhi(v2), h3 = bfhi(v3);
                *(uint32_t*)(Chi + (size_t)r0 * N + col)       = pack2bf(h0, h1);
                *(uint32_t*)(Clo + (size_t)r0 * N + col)       = pack2bf(v0 - h0, v1 - h1);
                *(uint32_t*)(Chi + (size_t)(r0 + 8) * N + col) = pack2bf(h2, h3);
                *(uint32_t*)(Clo + (size_t)(r0 + 8) * N + col) = pack2bf(v2 - h2, v3 - h3);
            }
        }
    }
}

// ---------------- per-segment attention (split bf16 output) ----------------
__global__ void attn_kernel(const float* __restrict__ q,
                            const float* __restrict__ k,
                            const float* __restrict__ v,
                            bf16* __restrict__ thi, bf16* __restrict__ tlo,
                            int start, int len)
{
    extern __shared__ float sm[];
    int bid = blockIdx.x;
    int hh = bid & 7;
    int b  = bid >> 3;
    int tid = threadIdx.x;        // 256
    int h64 = hh * HD;
    size_t rowbase = (size_t)b * LTOT + start;
    int lenp = len + 4;

    float* sQ  = sm;                       // len*64  (later V)
    float* sKt = sm + len * HD;            // 64*(len+4)
    float* sS  = sKt + HD * lenp;          // len*(len+4)

    for (int e = tid; e < len * HD; e += 256) {
        int l = e >> 6, kk = e & 63;
        size_t gi = (rowbase + l) * DM + h64 + kk;
        sQ[e] = q[gi];
        sKt[kk * lenp + l] = k[gi];
    }
    __syncthreads();

    int nq4 = len >> 2;
    for (int e = tid; e < len * nq4; e += 256) {
        int l  = e / nq4;
        int m4 = (e - l * nq4) * 4;
        const float* qr = sQ + l * HD;
        float ax = 0.0f, ay = 0.0f, az = 0.0f, aw = 0.0f;
        #pragma unroll 8
        for (int kk = 0; kk < HD; kk++) {
            float qv = qr[kk];
            float4 kv = *(const float4*)&sKt[kk * lenp + m4];
            ax += qv * kv.x; ay += qv * kv.y;
            az += qv * kv.z; aw += qv * kv.w;
        }
        float4 rr; rr.x = ax * 0.125f; rr.y = ay * 0.125f;
        rr.z = az * 0.125f; rr.w = aw * 0.125f;
        *(float4*)&sS[l * lenp + m4] = rr;
    }
    __syncthreads();

    for (int e = tid; e < len * HD; e += 256) {
        int l = e >> 6, kk = e & 63;
        sQ[e] = v[(rowbase + l) * DM + h64 + kk];
    }
    if (tid < len) {
        float* row = sS + tid * lenp;
        float mx = -1e30f;
        for (int m = 0; m < len; m++) mx = fmaxf(mx, row[m]);
        float sum = 0.0f;
        for (int m = 0; m < len; m++) {
            float ev = expf(row[m] - mx);
            row[m] = ev;
            sum += ev;
        }
        float inv = 1.0f / sum;
        for (int m = 0; m < len; m++) row[m] *= inv;
    }
    __syncthreads();

    for (int e = tid; e < len * (HD / 4); e += 256) {
        int l  = e >> 4;
        int d4 = (e & 15) * 4;
        const float* srow = sS + l * lenp;
        float ax = 0.0f, ay = 0.0f, az = 0.0f, aw = 0.0f;
        #pragma unroll 8
        for (int m = 0; m < len; m++) {
            float s = srow[m];
            float4 vv = *(const float4*)&sQ[m * HD + d4];
            ax += s * vv.x; ay += s * vv.y;
            az += s * vv.z; aw += s * vv.w;
        }
        size_t go = (rowbase + l) * DM + h64 + d4;
        float hx = bfhi(ax), hy = bfhi(ay), hz = bfhi(az), hw = bfhi(aw);
        *(uint2*)(thi + go) = make_uint2(pack2bf(hx, hy), pack2bf(hz, hw));
        *(uint2*)(tlo + go) = make_uint2(pack2bf(ax - hx, ay - hy), pack2bf(az - hz, aw - hw));
    }
}

// ---------------- residual + LayerNorm (+ optional split output) ----------------
__global__ void ln_kernel(const float* __restrict__ x, const float* __restrict__ res,
                          const float* __restrict__ g, const float* __restrict__ bb,
                          float* __restrict__ out,
                          bf16* __restrict__ ohi, bf16* __restrict__ olo,
                          int hasRes)
{
    int row = blockIdx.x;
    int tid = threadIdx.x;   // 128
    float4 vv = ((const float4*)(x + (size_t)row * DM))[tid];
    if (hasRes) {
        float4 rr = ((const float4*)(res + (size_t)row * DM))[tid];
        vv.x += rr.x; vv.y += rr.y; vv.z += rr.z; vv.w += rr.w;
    }
    float sum = vv.x + vv.y + vv.z + vv.w;
    float sq  = vv.x * vv.x + vv.y * vv.y + vv.z * vv.z + vv.w * vv.w;

    #pragma unroll
    for (int off = 16; off; off >>= 1) {
        sum += __shfl_xor_sync(0xFFFFFFFFu, sum, off);
        sq  += __shfl_xor_sync(0xFFFFFFFFu, sq,  off);
    }
    __shared__ float red[2][4];
    int w = tid >> 5;
    if ((tid & 31) == 0) { red[0][w] = sum; red[1][w] = sq; }
    __syncthreads();
    sum = red[0][0] + red[0][1] + red[0][2] + red[0][3];
    sq  = red[1][0] + red[1][1] + red[1][2] + red[1][3];

    float mean = sum * (1.0f / DM);
    float var  = sq * (1.0f / DM) - mean * mean;
    float rstd = rsqrtf(var + 1e-5f);

    float4 gv = ((const float4*)g)[tid];
    float4 bv = ((const float4*)bb)[tid];
    float4 ov;
    ov.x = (vv.x - mean) * rstd * gv.x + bv.x;
    ov.y = (vv.y - mean) * rstd * gv.y + bv.y;
    ov.z = (vv.z - mean) * rstd * gv.z + bv.z;
    ov.w = (vv.w - mean) * rstd * gv.w + bv.w;
    ((float4*)(out + (size_t)row * DM))[tid] = ov;

    if (ohi) {
        float hx = bfhi(ov.x), hy = bfhi(ov.y), hz = bfhi(ov.z), hw = bfhi(ov.w);
        ((uint2*)(ohi + (size_t)row * DM))[tid] =
            make_uint2(pack2bf(hx, hy), pack2bf(hz, hw));
        ((uint2*)(olo + (size_t)row * DM))[tid] =
            make_uint2(pack2bf(ov.x - hx, ov.y - hy), pack2bf(ov.z - hz, ov.w - hw));
    }
}

// ---------------- host launcher ----------------
extern "C" void kernel_launch(void* const* d_in, const int* in_sizes, int n_in,
                              void* d_out, int out_size)
{
    (void)in_sizes; (void)n_in; (void)out_size;
    const float* x_enc = (const float*)d_in[0];
    const float* W_emb = (const float*)d_in[1];
    const float* Wq    = (const float*)d_in[2];
    const float* bq    = (const float*)d_in[3];
    const float* Wk    = (const float*)d_in[4];
    const float* bk    = (const float*)d_in[5];
    const float* Wv    = (const float*)d_in[6];
    const float* bv    = (const float*)d_in[7];
    const float* Wo    = (const float*)d_in[8];
    const float* bo    = (const float*)d_in[9];
    const float* ln1_g = (const float*)d_in[10];
    const float* ln1_b = (const float*)d_in[11];
    const float* W1    = (const float*)d_in[12];
    const float* b1    = (const float*)d_in[13];
    const float* W2    = (const float*)d_in[14];
    const float* b2    = (const float*)d_in[15];
    const float* ln2_g = (const float*)d_in[16];
    const float* ln2_b = (const float*)d_in[17];
    const float* lnf_g = (const float*)d_in[18];
    const float* lnf_b = (const float*)d_in[19];

    float *h, *qb, *kb, *vb;
    bf16 *hhi, *hlo, *thi, *tlo, *fhi, *flo, *whi, *wlo;
    cudaGetSymbolAddress((void**)&h,   g_h);
    cudaGetSymbolAddress((void**)&qb,  g_q);
    cudaGetSymbolAddress((void**)&kb,  g_k);
    cudaGetSymbolAddress((void**)&vb,  g_v);
    cudaGetSymbolAddress((void**)&hhi, g_hhi);
    cudaGetSymbolAddress((void**)&hlo, g_hlo);
    cudaGetSymbolAddress((void**)&thi, g_thi);
    cudaGetSymbolAddress((void**)&tlo, g_tlo);
    cudaGetSymbolAddress((void**)&fhi, g_fhi);
    cudaGetSymbolAddress((void**)&flo, g_flo);
    cudaGetSymbolAddress((void**)&whi, g_whi);
    cudaGetSymbolAddress((void**)&wlo, g_wlo);

    cudaFuncSetAttribute(attn_kernel, cudaFuncAttributeMaxDynamicSharedMemorySize, 140000);
    cudaFuncSetAttribute(gemm_mma, cudaFuncAttributeMaxDynamicSharedMemorySize, GSMEM);

    // weight offsets in the split buffers
    const size_t WD = (size_t)DM * DM;          // 262144
    const size_t WF = (size_t)DM * DFF;         // 1048576
    const size_t OQ = 0, OKk = 3 * WD, OV = 6 * WD, OO = 9 * WD;
    const size_t O1 = 12 * WD, O2 = O1 + 3 * WF;

    // one-time (per launch) weight splitting
    wsplit_kernel<<<(int)(3 * WD / 4 + 255) / 256, 256>>>(Wq, whi + OQ,  wlo + OQ,  (int)(3 * WD / 4));
    wsplit_kernel<<<(int)(3 * WD / 4 + 255) / 256, 256>>>(Wk, whi + OKk, wlo + OKk, (int)(3 * WD / 4));
    wsplit_kernel<<<(int)(3 * WD / 4 + 255) / 256, 256>>>(Wv, whi + OV,  wlo + OV,  (int)(3 * WD / 4));
    wsplit_kernel<<<(int)(3 * WD / 4 + 255) / 256, 256>>>(Wo, whi + OO,  wlo + OO,  (int)(3 * WD / 4));
    wsplit_kernel<<<(int)(3 * WF / 4 + 255) / 256, 256>>>(W1, whi + O1,  wlo + O1,  (int)(3 * WF / 4));
    wsplit_kernel<<<(int)(3 * WF / 4 + 255) / 256, 256>>>(W2, whi + O2,  wlo + O2,  (int)(3 * WF / 4));

    embed_kernel<<<dim3(LTOT, BSEQ), 256>>>(x_enc, W_emb, h, hhi, hlo);

    const int segStart[4] = {0, 16, 48, 112};
    const int segLen[4]   = {16, 32, 64, 128};

    dim3 gD(DM / 128, MROWS / 128);    // (4, 480)
    dim3 gF(DFF / 128, MROWS / 128);   // (16, 480)

    for (int i = 0; i < NLAYERS; i++) {
        gemm_mma<<<gD, 256, GSMEM>>>(hhi, hlo, whi + OQ + i * WD, wlo + OQ + i * WD,
                                     bq + i * DM, qb, nullptr, nullptr, MROWS, DM, DM, 0);
        gemm_mma<<<gD, 256, GSMEM>>>(hhi, hlo, whi + OKk + i * WD, wlo + OKk + i * WD,
                                     bk + i * DM, kb, nullptr, nullptr, MROWS, DM, DM, 0);
        gemm_mma<<<gD, 256, GSMEM>>>(hhi, hlo, whi + OV + i * WD, wlo + OV + i * WD,
                                     bv + i * DM, vb, nullptr, nullptr, MROWS, DM, DM, 0);

        for (int s = 0; s < 4; s++) {
            int len = segLen[s];
            int lenp = len + 4;
            size_t smem = (size_t)(len * HD + HD * lenp + len * lenp) * sizeof(float);
            attn_kernel<<<BSEQ * NHEADS, 256, smem>>>(qb, kb, vb, thi, tlo, segStart[s], len);
        }

        gemm_mma<<<gD, 256, GSMEM>>>(thi, tlo, whi + OO + i * WD, wlo + OO + i * WD,
                                     bo + i * DM, qb, nullptr, nullptr, MROWS, DM, DM, 0);
        ln_kernel<<<MROWS, 128>>>(h, qb, ln1_g + i * DM, ln1_b + i * DM, h, hhi, hlo, 1);

        gemm_mma<<<gF, 256, GSMEM>>>(hhi, hlo, whi + O1 + i * WF, wlo + O1 + i * WF,
                                     b1 + i * DFF, nullptr, fhi, flo, MROWS, DFF, DM, 1);
        gemm_mma<<<gD, 256, GSMEM>>>(fhi, flo, whi + O2 + i * WF, wlo + O2 + i * WF,
                                     b2 + i * DM, qb, nullptr, nullptr, MROWS, DM, DFF, 0);
        ln_kernel<<<MROWS, 128>>>(h, qb, ln2_g + i * DM, ln2_b + i * DM, h, hhi, hlo, 1);
    }

    ln_kernel<<<MROWS, 128>>>(h, nullptr, lnf_g, lnf_b, (float*)d_out, nullptr, nullptr, 0);
}

// round 9
// speedup vs baseline: 1.2301x; 1.2301x over previous
#include <cuda_runtime.h>
#include <cuda_bf16.h>
#include <cstdint>

#define BS       8
#define CCH      32
#define TLEN     2048
#define PATCH_N  16
#define DM       512
#define NHEADS   8
#define HD       64
#define DFF      2048
#define NLAYERS  3
#define BSEQ     (BS * CCH)       // 256
#define LTOT     240
#define MROWS    (BSEQ * LTOT)    // 61440

typedef __nv_bfloat16 bf16;

// ---------------- scratch ----------------
__device__ float g_h [MROWS * DM];
__device__ float g_q [MROWS * DM];
__device__ float g_k [MROWS * DM];
__device__ float g_v [MROWS * DM];
__device__ bf16  g_hhi[MROWS * DM], g_hlo[MROWS * DM];
__device__ bf16  g_thi[MROWS * DM], g_tlo[MROWS * DM];
__device__ bf16  g_fhi[(size_t)MROWS * DFF], g_flo[(size_t)MROWS * DFF];
#define WTOT 9437184
__device__ bf16  g_whi[WTOT], g_wlo[WTOT];

// ---------------- helpers ----------------
__device__ __forceinline__ uint32_t smem_u32(const void* p) {
    uint32_t a;
    asm("{ .reg .u64 t; cvta.to.shared.u64 t, %1; cvt.u32.u64 %0, t; }"
        : "=r"(a) : "l"(p));
    return a;
}
__device__ __forceinline__ void cpasync16(uint32_t d, const void* s) {
    asm volatile("cp.async.cg.shared.global [%0], [%1], 16;"
                 :: "r"(d), "l"(s) : "memory");
}
__device__ __forceinline__ float gelu_tanh(float x) {
    float x3 = x * x * x;
    float t = tanhf(0.7978845608028654f * (x + 0.044715f * x3));
    return 0.5f * x * (1.0f + t);
}
__device__ __forceinline__ uint32_t pack2bf(float x, float y) {
    __nv_bfloat162 h = __floats2bfloat162_rn(x, y);
    return *reinterpret_cast<uint32_t*>(&h);
}
__device__ __forceinline__ float bfhi(float x) {
    return __bfloat162float(__float2bfloat16(x));
}

#define LDSM_X4(r0, r1, r2, r3, addr) \
    asm volatile("ldmatrix.sync.aligned.m8n8.x4.shared.b16 {%0,%1,%2,%3}, [%4];" \
                 : "=r"(r0), "=r"(r1), "=r"(r2), "=r"(r3) : "r"(addr))

#define LDSM_X4_T(r0, r1, r2, r3, addr) \
    asm volatile("ldmatrix.sync.aligned.m8n8.x4.trans.shared.b16 {%0,%1,%2,%3}, [%4];" \
                 : "=r"(r0), "=r"(r1), "=r"(r2), "=r"(r3) : "r"(addr))

#define MMA_BF16(d, a, b0v, b1v) \
    asm volatile("mma.sync.aligned.m16n8k16.row.col.f32.bf16.bf16.f32 " \
                 "{%0,%1,%2,%3}, {%4,%5,%6,%7}, {%8,%9}, {%0,%1,%2,%3};" \
                 : "+f"((d)[0]), "+f"((d)[1]), "+f"((d)[2]), "+f"((d)[3]) \
                 : "r"((a)[0]), "r"((a)[1]), "r"((a)[2]), "r"((a)[3]), \
                   "r"(b0v), "r"(b1v))

// ---------------- weight split ----------------
__global__ void wsplit_kernel(const float* __restrict__ w,
                              bf16* __restrict__ hi, bf16* __restrict__ lo, int n4)
{
    int i = blockIdx.x * 256 + threadIdx.x;
    if (i >= n4) return;
    float4 v = ((const float4*)w)[i];
    float hx = bfhi(v.x), hy = bfhi(v.y), hz = bfhi(v.z), hw = bfhi(v.w);
    ((uint2*)hi)[i] = make_uint2(pack2bf(hx, hy), pack2bf(hz, hw));
    ((uint2*)lo)[i] = make_uint2(pack2bf(v.x - hx, v.y - hy), pack2bf(v.z - hz, v.w - hw));
}

// ---------------- embedding ----------------
__global__ void embed_kernel(const float* __restrict__ x_enc,
                             const float* __restrict__ Wemb,
                             float* __restrict__ h,
                             bf16* __restrict__ hhi, bf16* __restrict__ hlo)
{
    int tok = blockIdx.x;
    int r   = blockIdx.y;
    int tid = threadIdx.x;
    int b  = r >> 5;
    int cc = r & 31;

    int kstr, j;
    if (tok < 16)       { kstr = 8; j = tok; }
    else if (tok < 48)  { kstr = 4; j = tok - 16; }
    else if (tok < 112) { kstr = 2; j = tok - 48; }
    else                { kstr = 1; j = tok - 112; }

    __shared__ float xv[PATCH_N];
    if (tid < PATCH_N) {
        int tt = kstr * (j * PATCH_N + tid);
        xv[tid] = x_enc[((size_t)b * TLEN + tt) * CCH + cc];
    }
    __syncthreads();

    float pepos = (float)(j * kstr);
    const float cln = 9.210340371976184f / (float)DM;

    for (int d = tid; d < DM; d += 256) {
        float acc = 0.0f;
        #pragma unroll
        for (int p = 0; p < PATCH_N; p++)
            acc += xv[p] * Wemb[p * DM + d];
        int i2 = d & ~1;
        float ang = pepos * __expf(-(float)i2 * cln);
        float pv = (d & 1) ? cosf(ang) : sinf(ang);
        float val = acc + pv;
        size_t gi = ((size_t)r * LTOT + tok) * DM + d;
        h[gi] = val;
        float hx = bfhi(val);
        hhi[gi] = __float2bfloat16(hx);
        hlo[gi] = __float2bfloat16(val - hx);
    }
}

// ---------------- mma.sync bf16x3 GEMM, 4 warps of 64x64, 2 CTAs/SM ----------------
#define AST 40          // A smem stride (elems): 32 + 8 pad -> 80B
#define BST 136         // B smem stride (elems): 128 + 8 pad -> 272B
#define STAGE_AH 0
#define STAGE_AL 10240  // bytes
#define STAGE_BH 20480
#define STAGE_BL 29184
#define STAGEB   37888
#define GSMEM    (2 * STAGEB)   // 75776 bytes

__global__ __launch_bounds__(128, 2)
void gemm_mma(const bf16* __restrict__ Ahi, const bf16* __restrict__ Alo,
              const bf16* __restrict__ Bhi, const bf16* __restrict__ Blo,
              const float* __restrict__ bias,
              float* __restrict__ C, bf16* __restrict__ Chi, bf16* __restrict__ Clo,
              int M, int N, int K, int doGelu)
{
    extern __shared__ char dsm[];
    uint32_t dynb = smem_u32(dsm);

    int tid  = threadIdx.x;
    int wid  = tid >> 5;    // 0..3
    int lane = tid & 31;
    int wm = wid & 1;       // 2 row groups of 64
    int wn = wid >> 1;      // 2 col groups of 64
    int m0 = blockIdx.y * 128;
    int n0 = blockIdx.x * 128;

    float acc[4][8][4];
    #pragma unroll
    for (int i = 0; i < 4; i++)
        #pragma unroll
        for (int j = 0; j < 8; j++)
            #pragma unroll
            for (int c = 0; c < 4; c++) acc[i][j][c] = 0.0f;

    // per-lane ldmatrix offsets (bytes, relative to tile base)
    uint32_t aoffL = ((uint32_t)((wm * 64 + (lane & 15)) * AST + (lane >> 4) * 8)) * 2;
    uint32_t boffL = ((uint32_t)(((lane & 7) + ((lane >> 3) & 1) * 8) * BST
                                 + wn * 64 + (lane >> 4) * 8)) * 2;

    int nslab = K >> 5;

    auto issue = [&](int j, int s) {
        uint32_t sb = dynb + (uint32_t)s * STAGEB;
        int k0 = j * 32;
        #pragma unroll
        for (int i = 0; i < 4; i++) {
            int chunk = i * 128 + tid;
            int row = chunk >> 2, c8 = (chunk & 3) * 8;
            uint32_t off = (uint32_t)(row * AST + c8) * 2;
            size_t gi = (size_t)(m0 + row) * K + k0 + c8;
            cpasync16(sb + STAGE_AH + off, Ahi + gi);
            cpasync16(sb + STAGE_AL + off, Alo + gi);
        }
        #pragma unroll
        for (int i = 0; i < 4; i++) {
            int chunk = i * 128 + tid;
            int row = chunk >> 4, c8 = (chunk & 15) * 8;
            uint32_t off = (uint32_t)(row * BST + c8) * 2;
            size_t gi = (size_t)(k0 + row) * N + n0 + c8;
            cpasync16(sb + STAGE_BH + off, Bhi + gi);
            cpasync16(sb + STAGE_BL + off, Blo + gi);
        }
        asm volatile("cp.async.commit_group;" ::: "memory");
    };

    issue(0, 0);
    for (int j = 0; j < nslab; j++) {
        if (j + 1 < nslab) {
            issue(j + 1, (j + 1) & 1);
            asm volatile("cp.async.wait_group 1;" ::: "memory");
        } else {
            asm volatile("cp.async.wait_group 0;" ::: "memory");
        }
        __syncthreads();

        uint32_t sb = dynb + (uint32_t)(j & 1) * STAGEB;
        uint32_t aH = sb + STAGE_AH, aL = sb + STAGE_AL;
        uint32_t bH = sb + STAGE_BH, bL = sb + STAGE_BL;

        #pragma unroll
        for (int ks = 0; ks < 2; ks++) {
            uint32_t kbA = (uint32_t)(ks * 16) * 2;
            uint32_t kbB = (uint32_t)(ks * 16 * BST) * 2;

            uint32_t ah[4][4], al[4][4];
            #pragma unroll
            for (int mf = 0; mf < 4; mf++) {
                uint32_t off = aoffL + (uint32_t)(mf * 16 * AST) * 2 + kbA;
                LDSM_X4(ah[mf][0], ah[mf][1], ah[mf][2], ah[mf][3], aH + off);
                LDSM_X4(al[mf][0], al[mf][1], al[mf][2], al[mf][3], aL + off);
            }
            uint32_t bh[16], bl[16];
            #pragma unroll
            for (int nb = 0; nb < 4; nb++) {
                uint32_t off = boffL + (uint32_t)(nb * 16) * 2 + kbB;
                LDSM_X4_T(bh[nb * 4 + 0], bh[nb * 4 + 1], bh[nb * 4 + 2], bh[nb * 4 + 3], bH + off);
                LDSM_X4_T(bl[nb * 4 + 0], bl[nb * 4 + 1], bl[nb * 4 + 2], bl[nb * 4 + 3], bL + off);
            }

            #pragma unroll
            for (int mf = 0; mf < 4; mf++)
                #pragma unroll
                for (int nf = 0; nf < 8; nf++) {
                    MMA_BF16(acc[mf][nf], ah[mf], bh[nf * 2], bh[nf * 2 + 1]);
                    MMA_BF16(acc[mf][nf], ah[mf], bl[nf * 2], bl[nf * 2 + 1]);
                    MMA_BF16(acc[mf][nf], al[mf], bh[nf * 2], bh[nf * 2 + 1]);
                }
        }
        __syncthreads();
    }

    // epilogue
    int rbase = m0 + wm * 64 + (lane >> 2);
    int cbase = n0 + wn * 64 + (lane & 3) * 2;
    #pragma unroll
    for (int mf = 0; mf < 4; mf++) {
        #pragma unroll
        for (int nf = 0; nf < 8; nf++) {
            int col = cbase + nf * 8;
            float b0v = bias[col], b1v = bias[col + 1];
            float v0 = acc[mf][nf][0] + b0v;
            float v1 = acc[mf][nf][1] + b1v;
            float v2 = acc[mf][nf][2] + b0v;
            float v3 = acc[mf][nf][3] + b1v;
            if (doGelu) {
                v0 = gelu_tanh(v0); v1 = gelu_tanh(v1);
                v2 = gelu_tanh(v2); v3 = gelu_tanh(v3);
            }
            int r0 = rbase + mf * 16;
            if (C) {
                *(float2*)(C + (size_t)r0 * N + col)       = make_float2(v0, v1);
                *(float2*)(C + (size_t)(r0 + 8) * N + col) = make_float2(v2, v3);
            }
            if (Chi) {
                float h0 = bfhi(v0), h1 = bfhi(v1), h2 = bfhi(v2), h3 = bfhi(v3);
                *(uint32_t*)(Chi + (size_t)r0 * N + col)       = pack2bf(h0, h1);
                *(uint32_t*)(Clo + (size_t)r0 * N + col)       = pack2bf(v0 - h0, v1 - h1);
                *(uint32_t*)(Chi + (size_t)(r0 + 8) * N + col) = pack2bf(h2, h3);
                *(uint32_t*)(Clo + (size_t)(r0 + 8) * N + col) = pack2bf(v2 - h2, v3 - h3);
            }
        }
    }
}

// ---------------- per-segment attention (split bf16 output) ----------------
__global__ void attn_kernel(const float* __restrict__ q,
                            const float* __restrict__ k,
                            const float* __restrict__ v,
                            bf16* __restrict__ thi, bf16* __restrict__ tlo,
                            int start, int len)
{
    extern __shared__ float sm[];
    int bid = blockIdx.x;
    int hh = bid & 7;
    int b  = bid >> 3;
    int tid = threadIdx.x;        // 256
    int h64 = hh * HD;
    size_t rowbase = (size_t)b * LTOT + start;
    int lenp = len + 4;

    float* sQ  = sm;                       // len*64  (later V)
    float* sKt = sm + len * HD;            // 64*(len+4)
    float* sS  = sKt + HD * lenp;          // len*(len+4)

    for (int e = tid; e < len * HD; e += 256) {
        int l = e >> 6, kk = e & 63;
        size_t gi = (rowbase + l) * DM + h64 + kk;
        sQ[e] = q[gi];
        sKt[kk * lenp + l] = k[gi];
    }
    __syncthreads();

    int nq4 = len >> 2;
    for (int e = tid; e < len * nq4; e += 256) {
        int l  = e / nq4;
        int m4 = (e - l * nq4) * 4;
        const float* qr = sQ + l * HD;
        float ax = 0.0f, ay = 0.0f, az = 0.0f, aw = 0.0f;
        #pragma unroll 8
        for (int kk = 0; kk < HD; kk++) {
            float qv = qr[kk];
            float4 kv = *(const float4*)&sKt[kk * lenp + m4];
            ax += qv * kv.x; ay += qv * kv.y;
            az += qv * kv.z; aw += qv * kv.w;
        }
        float4 rr; rr.x = ax * 0.125f; rr.y = ay * 0.125f;
        rr.z = az * 0.125f; rr.w = aw * 0.125f;
        *(float4*)&sS[l * lenp + m4] = rr;
    }
    __syncthreads();

    for (int e = tid; e < len * HD; e += 256) {
        int l = e >> 6, kk = e & 63;
        sQ[e] = v[(rowbase + l) * DM + h64 + kk];
    }
    if (tid < len) {
        float* row = sS + tid * lenp;
        float mx = -1e30f;
        for (int m = 0; m < len; m++) mx = fmaxf(mx, row[m]);
        float sum = 0.0f;
        for (int m = 0; m < len; m++) {
            float ev = expf(row[m] - mx);
            row[m] = ev;
            sum += ev;
        }
        float inv = 1.0f / sum;
        for (int m = 0; m < len; m++) row[m] *= inv;
    }
    __syncthreads();

    for (int e = tid; e < len * (HD / 4); e += 256) {
        int l  = e >> 4;
        int d4 = (e & 15) * 4;
        const float* srow = sS + l * lenp;
        float ax = 0.0f, ay = 0.0f, az = 0.0f, aw = 0.0f;
        #pragma unroll 8
        for (int m = 0; m < len; m++) {
            float s = srow[m];
            float4 vv = *(const float4*)&sQ[m * HD + d4];
            ax += s * vv.x; ay += s * vv.y;
            az += s * vv.z; aw += s * vv.w;
        }
        size_t go = (rowbase + l) * DM + h64 + d4;
        float hx = bfhi(ax), hy = bfhi(ay), hz = bfhi(az), hw = bfhi(aw);
        *(uint2*)(thi + go) = make_uint2(pack2bf(hx, hy), pack2bf(hz, hw));
        *(uint2*)(tlo + go) = make_uint2(pack2bf(ax - hx, ay - hy), pack2bf(az - hz, aw - hw));
    }
}

// ---------------- residual + LayerNorm (+ optional split output) ----------------
__global__ void ln_kernel(const float* __restrict__ x, const float* __restrict__ res,
                          const float* __restrict__ g, const float* __restrict__ bb,
                          float* __restrict__ out,
                          bf16* __restrict__ ohi, bf16* __restrict__ olo,
                          int hasRes)
{
    int row = blockIdx.x;
    int tid = threadIdx.x;   // 128
    float4 vv = ((const float4*)(x + (size_t)row * DM))[tid];
    if (hasRes) {
        float4 rr = ((const float4*)(res + (size_t)row * DM))[tid];
        vv.x += rr.x; vv.y += rr.y; vv.z += rr.z; vv.w += rr.w;
    }
    float sum = vv.x + vv.y + vv.z + vv.w;
    float sq  = vv.x * vv.x + vv.y * vv.y + vv.z * vv.z + vv.w * vv.w;

    #pragma unroll
    for (int off = 16; off; off >>= 1) {
        sum += __shfl_xor_sync(0xFFFFFFFFu, sum, off);
        sq  += __shfl_xor_sync(0xFFFFFFFFu, sq,  off);
    }
    __shared__ float red[2][4];
    int w = tid >> 5;
    if ((tid & 31) == 0) { red[0][w] = sum; red[1][w] = sq; }
    __syncthreads();
    sum = red[0][0] + red[0][1] + red[0][2] + red[0][3];
    sq  = red[1][0] + red[1][1] + red[1][2] + red[1][3];

    float mean = sum * (1.0f / DM);
    float var  = sq * (1.0f / DM) - mean * mean;
    float rstd = rsqrtf(var + 1e-5f);

    float4 gv = ((const float4*)g)[tid];
    float4 bv = ((const float4*)bb)[tid];
    float4 ov;
    ov.x = (vv.x - mean) * rstd * gv.x + bv.x;
    ov.y = (vv.y - mean) * rstd * gv.y + bv.y;
    ov.z = (vv.z - mean) * rstd * gv.z + bv.z;
    ov.w = (vv.w - mean) * rstd * gv.w + bv.w;
    ((float4*)(out + (size_t)row * DM))[tid] = ov;

    if (ohi) {
        float hx = bfhi(ov.x), hy = bfhi(ov.y), hz = bfhi(ov.z), hw = bfhi(ov.w);
        ((uint2*)(ohi + (size_t)row * DM))[tid] =
            make_uint2(pack2bf(hx, hy), pack2bf(hz, hw));
        ((uint2*)(olo + (size_t)row * DM))[tid] =
            make_uint2(pack2bf(ov.x - hx, ov.y - hy), pack2bf(ov.z - hz, ov.w - hw));
    }
}

// ---------------- host launcher ----------------
extern "C" void kernel_launch(void* const* d_in, const int* in_sizes, int n_in,
                              void* d_out, int out_size)
{
    (void)in_sizes; (void)n_in; (void)out_size;
    const float* x_enc = (const float*)d_in[0];
    const float* W_emb = (const float*)d_in[1];
    const float* Wq    = (const float*)d_in[2];
    const float* bq    = (const float*)d_in[3];
    const float* Wk    = (const float*)d_in[4];
    const float* bk    = (const float*)d_in[5];
    const float* Wv    = (const float*)d_in[6];
    const float* bv    = (const float*)d_in[7];
    const float* Wo    = (const float*)d_in[8];
    const float* bo    = (const float*)d_in[9];
    const float* ln1_g = (const float*)d_in[10];
    const float* ln1_b = (const float*)d_in[11];
    const float* W1    = (const float*)d_in[12];
    const float* b1    = (const float*)d_in[13];
    const float* W2    = (const float*)d_in[14];
    const float* b2    = (const float*)d_in[15];
    const float* ln2_g = (const float*)d_in[16];
    const float* ln2_b = (const float*)d_in[17];
    const float* lnf_g = (const float*)d_in[18];
    const float* lnf_b = (const float*)d_in[19];

    float *h, *qb, *kb, *vb;
    bf16 *hhi, *hlo, *thi, *tlo, *fhi, *flo, *whi, *wlo;
    cudaGetSymbolAddress((void**)&h,   g_h);
    cudaGetSymbolAddress((void**)&qb,  g_q);
    cudaGetSymbolAddress((void**)&kb,  g_k);
    cudaGetSymbolAddress((void**)&vb,  g_v);
    cudaGetSymbolAddress((void**)&hhi, g_hhi);
    cudaGetSymbolAddress((void**)&hlo, g_hlo);
    cudaGetSymbolAddress((void**)&thi, g_thi);
    cudaGetSymbolAddress((void**)&tlo, g_tlo);
    cudaGetSymbolAddress((void**)&fhi, g_fhi);
    cudaGetSymbolAddress((void**)&flo, g_flo);
    cudaGetSymbolAddress((void**)&whi, g_whi);
    cudaGetSymbolAddress((void**)&wlo, g_wlo);

    cudaFuncSetAttribute(attn_kernel, cudaFuncAttributeMaxDynamicSharedMemorySize, 140000);
    cudaFuncSetAttribute(gemm_mma, cudaFuncAttributeMaxDynamicSharedMemorySize, GSMEM);

    const size_t WD = (size_t)DM * DM;          // 262144
    const size_t WF = (size_t)DM * DFF;         // 1048576
    const size_t OQ = 0, OKk = 3 * WD, OV = 6 * WD, OO = 9 * WD;
    const size_t O1 = 12 * WD, O2 = O1 + 3 * WF;

    wsplit_kernel<<<(int)(3 * WD / 4 + 255) / 256, 256>>>(Wq, whi + OQ,  wlo + OQ,  (int)(3 * WD / 4));
    wsplit_kernel<<<(int)(3 * WD / 4 + 255) / 256, 256>>>(Wk, whi + OKk, wlo + OKk, (int)(3 * WD / 4));
    wsplit_kernel<<<(int)(3 * WD / 4 + 255) / 256, 256>>>(Wv, whi + OV,  wlo + OV,  (int)(3 * WD / 4));
    wsplit_kernel<<<(int)(3 * WD / 4 + 255) / 256, 256>>>(Wo, whi + OO,  wlo + OO,  (int)(3 * WD / 4));
    wsplit_kernel<<<(int)(3 * WF / 4 + 255) / 256, 256>>>(W1, whi + O1,  wlo + O1,  (int)(3 * WF / 4));
    wsplit_kernel<<<(int)(3 * WF / 4 + 255) / 256, 256>>>(W2, whi + O2,  wlo + O2,  (int)(3 * WF / 4));

    embed_kernel<<<dim3(LTOT, BSEQ), 256>>>(x_enc, W_emb, h, hhi, hlo);

    const int segStart[4] = {0, 16, 48, 112};
    const int segLen[4]   = {16, 32, 64, 128};

    dim3 gD(DM / 128, MROWS / 128);    // (4, 480)
    dim3 gF(DFF / 128, MROWS / 128);   // (16, 480)

    for (int i = 0; i < NLAYERS; i++) {
        gemm_mma<<<gD, 128, GSMEM>>>(hhi, hlo, whi + OQ + i * WD, wlo + OQ + i * WD,
                                     bq + i * DM, qb, nullptr, nullptr, MROWS, DM, DM, 0);
        gemm_mma<<<gD, 128, GSMEM>>>(hhi, hlo, whi + OKk + i * WD, wlo + OKk + i * WD,
                                     bk + i * DM, kb, nullptr, nullptr, MROWS, DM, DM, 0);
        gemm_mma<<<gD, 128, GSMEM>>>(hhi, hlo, whi + OV + i * WD, wlo + OV + i * WD,
                                     bv + i * DM, vb, nullptr, nullptr, MROWS, DM, DM, 0);

        for (int s = 0; s < 4; s++) {
            int len = segLen[s];
            int lenp = len + 4;
            size_t smem = (size_t)(len * HD + HD * lenp + len * lenp) * sizeof(float);
            attn_kernel<<<BSEQ * NHEADS, 256, smem>>>(qb, kb, vb, thi, tlo, segStart[s], len);
        }

        gemm_mma<<<gD, 128, GSMEM>>>(thi, tlo, whi + OO + i * WD, wlo + OO + i * WD,
                                     bo + i * DM, qb, nullptr, nullptr, MROWS, DM, DM, 0);
        ln_kernel<<<MROWS, 128>>>(h, qb, ln1_g + i * DM, ln1_b + i * DM, h, hhi, hlo, 1);

        gemm_mma<<<gF, 128, GSMEM>>>(hhi, hlo, whi + O1 + i * WF, wlo + O1 + i * WF,
                                     b1 + i * DFF, nullptr, fhi, flo, MROWS, DFF, DM, 1);
        gemm_mma<<<gD, 128, GSMEM>>>(fhi, flo, whi + O2 + i * WF, wlo + O2 + i * WF,
                                     b2 + i * DM, qb, nullptr, nullptr, MROWS, DM, DFF, 0);
        ln_kernel<<<MROWS, 128>>>(h, qb, ln2_g + i * DM, ln2_b + i * DM, h, hhi, hlo, 1);
    }

    ln_kernel<<<MROWS, 128>>>(h, nullptr, lnf_g, lnf_b, (float*)d_out, nullptr, nullptr, 0);
}

// round 11
// speedup vs baseline: 1.2542x; 1.0196x over previous
#include <cuda_runtime.h>
#include <cuda_bf16.h>
#include <cstdint>

#define BS       8
#define CCH      32
#define TLEN     2048
#define PATCH_N  16
#define DM       512
#define NHEADS   8
#define HD       64
#define DFF      2048
#define NLAYERS  3
#define BSEQ     (BS * CCH)       // 256
#define LTOT     240
#define MROWS    (BSEQ * LTOT)    // 61440
#define QKVS     1536

typedef __nv_bfloat16 bf16;

// ---------------- scratch ----------------
__device__ float g_h  [MROWS * DM];
__device__ float g_o  [MROWS * DM];
__device__ float g_qkv[(size_t)MROWS * QKVS];
__device__ float g_bqkv[NLAYERS * QKVS];
__device__ bf16  g_hhi[MROWS * DM], g_hlo[MROWS * DM];
__device__ bf16  g_thi[MROWS * DM], g_tlo[MROWS * DM];
__device__ bf16  g_fhi[(size_t)MROWS * DFF], g_flo[(size_t)MROWS * DFF];
#define WTOT 9437184
__device__ bf16  g_whi[WTOT], g_wlo[WTOT];

// ---------------- helpers ----------------
__device__ __forceinline__ uint32_t smem_u32(const void* p) {
    uint32_t a;
    asm("{ .reg .u64 t; cvta.to.shared.u64 t, %1; cvt.u32.u64 %0, t; }"
        : "=r"(a) : "l"(p));
    return a;
}
__device__ __forceinline__ void cpasync16(uint32_t d, const void* s) {
    asm volatile("cp.async.cg.shared.global [%0], [%1], 16;"
                 :: "r"(d), "l"(s) : "memory");
}
__device__ __forceinline__ float gelu_tanh(float x) {
    float x3 = x * x * x;
    float t = tanhf(0.7978845608028654f * (x + 0.044715f * x3));
    return 0.5f * x * (1.0f + t);
}
__device__ __forceinline__ uint32_t pack2bf(float x, float y) {
    __nv_bfloat162 h = __floats2bfloat162_rn(x, y);
    return *reinterpret_cast<uint32_t*>(&h);
}
__device__ __forceinline__ float bfhi(float x) {
    return __bfloat162float(__float2bfloat16(x));
}

#define LDSM_X4(r0, r1, r2, r3, addr) \
    asm volatile("ldmatrix.sync.aligned.m8n8.x4.shared.b16 {%0,%1,%2,%3}, [%4];" \
                 : "=r"(r0), "=r"(r1), "=r"(r2), "=r"(r3) : "r"(addr))

#define LDSM_X4_T(r0, r1, r2, r3, addr) \
    asm volatile("ldmatrix.sync.aligned.m8n8.x4.trans.shared.b16 {%0,%1,%2,%3}, [%4];" \
                 : "=r"(r0), "=r"(r1), "=r"(r2), "=r"(r3) : "r"(addr))

#define MMA_BF16(d, a, b0v, b1v) \
    asm volatile("mma.sync.aligned.m16n8k16.row.col.f32.bf16.bf16.f32 " \
                 "{%0,%1,%2,%3}, {%4,%5,%6,%7}, {%8,%9}, {%0,%1,%2,%3};" \
                 : "+f"((d)[0]), "+f"((d)[1]), "+f"((d)[2]), "+f"((d)[3]) \
                 : "r"((a)[0]), "r"((a)[1]), "r"((a)[2]), "r"((a)[3]), \
                   "r"(b0v), "r"(b1v))

// ---------------- weight splits ----------------
__global__ void wsplit_kernel(const float* __restrict__ w,
                              bf16* __restrict__ hi, bf16* __restrict__ lo, int n4)
{
    int i = blockIdx.x * 256 + threadIdx.x;
    if (i >= n4) return;
    float4 v = ((const float4*)w)[i];
    float hx = bfhi(v.x), hy = bfhi(v.y), hz = bfhi(v.z), hw = bfhi(v.w);
    ((uint2*)hi)[i] = make_uint2(pack2bf(hx, hy), pack2bf(hz, hw));
    ((uint2*)lo)[i] = make_uint2(pack2bf(v.x - hx, v.y - hy), pack2bf(v.z - hz, v.w - hw));
}

// combined Wq|Wk|Wv split into [L][512][1536]
__global__ void wsplit_qkv(const float* __restrict__ Wq, const float* __restrict__ Wk,
                           const float* __restrict__ Wv,
                           bf16* __restrict__ hi, bf16* __restrict__ lo)
{
    int i = blockIdx.x * 256 + threadIdx.x;        // float4 index in [3][512][384]
    if (i >= NLAYERS * 512 * (QKVS / 4)) return;
    int c4 = i % (QKVS / 4);
    int rem = i / (QKVS / 4);
    int k = rem % 512, L = rem / 512;
    int c = c4 * 4;
    const float* src;
    if (c < 512)        src = Wq + ((size_t)L * 512 + k) * 512 + c;
    else if (c < 1024)  src = Wk + ((size_t)L * 512 + k) * 512 + (c - 512);
    else                src = Wv + ((size_t)L * 512 + k) * 512 + (c - 1024);
    float4 v = *(const float4*)src;
    float hx = bfhi(v.x), hy = bfhi(v.y), hz = bfhi(v.z), hw = bfhi(v.w);
    ((uint2*)hi)[i] = make_uint2(pack2bf(hx, hy), pack2bf(hz, hw));
    ((uint2*)lo)[i] = make_uint2(pack2bf(v.x - hx, v.y - hy), pack2bf(v.z - hz, v.w - hw));
}

__global__ void packbias_kernel(const float* __restrict__ bq, const float* __restrict__ bk,
                                const float* __restrict__ bv, float* __restrict__ out)
{
    int i = blockIdx.x * 256 + threadIdx.x;
    if (i >= NLAYERS * QKVS) return;
    int L = i / QKVS, c = i % QKVS;
    float v = (c < 512) ? bq[L * 512 + c]
            : (c < 1024) ? bk[L * 512 + c - 512]
                         : bv[L * 512 + c - 1024];
    out[i] = v;
}

// ---------------- embedding ----------------
__global__ void embed_kernel(const float* __restrict__ x_enc,
                             const float* __restrict__ Wemb,
                             float* __restrict__ h,
                             bf16* __restrict__ hhi, bf16* __restrict__ hlo)
{
    int tok = blockIdx.x;
    int r   = blockIdx.y;
    int tid = threadIdx.x;
    int b  = r >> 5;
    int cc = r & 31;

    int kstr, j;
    if (tok < 16)       { kstr = 8; j = tok; }
    else if (tok < 48)  { kstr = 4; j = tok - 16; }
    else if (tok < 112) { kstr = 2; j = tok - 48; }
    else                { kstr = 1; j = tok - 112; }

    __shared__ float xv[PATCH_N];
    if (tid < PATCH_N) {
        int tt = kstr * (j * PATCH_N + tid);
        xv[tid] = x_enc[((size_t)b * TLEN + tt) * CCH + cc];
    }
    __syncthreads();

    float pepos = (float)(j * kstr);
    const float cln = 9.210340371976184f / (float)DM;

    for (int d = tid; d < DM; d += 256) {
        float acc = 0.0f;
        #pragma unroll
        for (int p = 0; p < PATCH_N; p++)
            acc += xv[p] * Wemb[p * DM + d];
        int i2 = d & ~1;
        float ang = pepos * __expf(-(float)i2 * cln);
        float pv = (d & 1) ? cosf(ang) : sinf(ang);
        float val = acc + pv;
        size_t gi = ((size_t)r * LTOT + tok) * DM + d;
        h[gi] = val;
        float hx = bfhi(val);
        hhi[gi] = __float2bfloat16(hx);
        hlo[gi] = __float2bfloat16(val - hx);
    }
}

// ---------------- mma.sync bf16x3 GEMM, 4 warps 64x64, 3-stage cp.async ----------------
#define AST 40          // A smem row stride (elems): 32 + 8 pad -> 80B
#define BST 136         // B smem row stride (elems): 128 + 8 pad -> 272B
#define STAGE_AH 0
#define STAGE_AL 10240  // bytes
#define STAGE_BH 20480
#define STAGE_BL 29184
#define STAGEB   37888
#define NSTG     3
#define GSMEM    (NSTG * STAGEB)   // 113664 bytes

__global__ __launch_bounds__(128, 2)
void gemm_mma(const bf16* __restrict__ Ahi, const bf16* __restrict__ Alo,
              const bf16* __restrict__ Bhi, const bf16* __restrict__ Blo,
              const float* __restrict__ bias,
              float* __restrict__ C, bf16* __restrict__ Chi, bf16* __restrict__ Clo,
              int M, int N, int K, int doGelu)
{
    extern __shared__ char dsm[];
    uint32_t dynb = smem_u32(dsm);

    int tid  = threadIdx.x;
    int wid  = tid >> 5;    // 0..3
    int lane = tid & 31;
    int wm = wid & 1;       // 2 row groups of 64
    int wn = wid >> 1;      // 2 col groups of 64
    int m0 = blockIdx.y * 128;
    int n0 = blockIdx.x * 128;

    float acc[4][8][4];
    #pragma unroll
    for (int i = 0; i < 4; i++)
        #pragma unroll
        for (int j = 0; j < 8; j++)
            #pragma unroll
            for (int c = 0; c < 4; c++) acc[i][j][c] = 0.0f;

    uint32_t aoffL = ((uint32_t)((wm * 64 + (lane & 15)) * AST + (lane >> 4) * 8)) * 2;
    uint32_t boffL = ((uint32_t)(((lane & 7) + ((lane >> 3) & 1) * 8) * BST
                                 + wn * 64 + (lane >> 4) * 8)) * 2;

    int nslab = K >> 5;

    auto issue = [&](int j) {
        uint32_t sb = dynb + (uint32_t)(j % NSTG) * STAGEB;
        int k0 = j * 32;
        #pragma unroll
        for (int i = 0; i < 4; i++) {
            int chunk = i * 128 + tid;
            int row = chunk >> 2, c8 = (chunk & 3) * 8;
            uint32_t off = (uint32_t)(row * AST + c8) * 2;
            size_t gi = (size_t)(m0 + row) * K + k0 + c8;
            cpasync16(sb + STAGE_AH + off, Ahi + gi);
            cpasync16(sb + STAGE_AL + off, Alo + gi);
        }
        #pragma unroll
        for (int i = 0; i < 4; i++) {
            int chunk = i * 128 + tid;
            int row = chunk >> 4, c8 = (chunk & 15) * 8;
            uint32_t off = (uint32_t)(row * BST + c8) * 2;
            size_t gi = (size_t)(k0 + row) * N + n0 + c8;
            cpasync16(sb + STAGE_BH + off, Bhi + gi);
            cpasync16(sb + STAGE_BL + off, Blo + gi);
        }
        asm volatile("cp.async.commit_group;" ::: "memory");
    };

    issue(0);
    issue(1);
    for (int j = 0; j < nslab; j++) {
        if (j + 1 < nslab)
            asm volatile("cp.async.wait_group 1;" ::: "memory");
        else
            asm volatile("cp.async.wait_group 0;" ::: "memory");
        __syncthreads();

        uint32_t sb = dynb + (uint32_t)(j % NSTG) * STAGEB;
        uint32_t aH = sb + STAGE_AH, aL = sb + STAGE_AL;
        uint32_t bH = sb + STAGE_BH, bL = sb + STAGE_BL;

        #pragma unroll
        for (int ks = 0; ks < 2; ks++) {
            uint32_t kbA = (uint32_t)(ks * 16) * 2;
            uint32_t kbB = (uint32_t)(ks * 16 * BST) * 2;

            uint32_t ah[4][4], al[4][4];
            #pragma unroll
            for (int mf = 0; mf < 4; mf++) {
                uint32_t off = aoffL + (uint32_t)(mf * 16 * AST) * 2 + kbA;
                LDSM_X4(ah[mf][0], ah[mf][1], ah[mf][2], ah[mf][3], aH + off);
                LDSM_X4(al[mf][0], al[mf][1], al[mf][2], al[mf][3], aL + off);
            }
            uint32_t bh[16], bl[16];
            #pragma unroll
            for (int nb = 0; nb < 4; nb++) {
                uint32_t off = boffL + (uint32_t)(nb * 16) * 2 + kbB;
                LDSM_X4_T(bh[nb * 4 + 0], bh[nb * 4 + 1], bh[nb * 4 + 2], bh[nb * 4 + 3], bH + off);
                LDSM_X4_T(bl[nb * 4 + 0], bl[nb * 4 + 1], bl[nb * 4 + 2], bl[nb * 4 + 3], bL + off);
            }

            #pragma unroll
            for (int mf = 0; mf < 4; mf++)
                #pragma unroll
                for (int nf = 0; nf < 8; nf++) {
                    MMA_BF16(acc[mf][nf], ah[mf], bh[nf * 2], bh[nf * 2 + 1]);
                    MMA_BF16(acc[mf][nf], ah[mf], bl[nf * 2], bl[nf * 2 + 1]);
                    MMA_BF16(acc[mf][nf], al[mf], bh[nf * 2], bh[nf * 2 + 1]);
                }
        }
        if (j + 2 < nslab) issue(j + 2);
    }

    // epilogue
    int rbase = m0 + wm * 64 + (lane >> 2);
    int cbase = n0 + wn * 64 + (lane & 3) * 2;
    #pragma unroll
    for (int mf = 0; mf < 4; mf++) {
        #pragma unroll
        for (int nf = 0; nf < 8; nf++) {
            int col = cbase + nf * 8;
            float b0v = bias[col], b1v = bias[col + 1];
            float v0 = acc[mf][nf][0] + b0v;
            float v1 = acc[mf][nf][1] + b1v;
            float v2 = acc[mf][nf][2] + b0v;
            float v3 = acc[mf][nf][3] + b1v;
            if (doGelu) {
                v0 = gelu_tanh(v0); v1 = gelu_tanh(v1);
                v2 = gelu_tanh(v2); v3 = gelu_tanh(v3);
            }
            int r0 = rbase + mf * 16;
            if (C) {
                *(float2*)(C + (size_t)r0 * N + col)       = make_float2(v0, v1);
                *(float2*)(C + (size_t)(r0 + 8) * N + col) = make_float2(v2, v3);
            }
            if (Chi) {
                float h0 = bfhi(v0), h1 = bfhi(v1), h2 = bfhi(v2), h3 = bfhi(v3);
                *(uint32_t*)(Chi + (size_t)r0 * N + col)       = pack2bf(h0, h1);
                *(uint32_t*)(Clo + (size_t)r0 * N + col)       = pack2bf(v0 - h0, v1 - h1);
                *(uint32_t*)(Chi + (size_t)(r0 + 8) * N + col) = pack2bf(h2, h3);
                *(uint32_t*)(Clo + (size_t)(r0 + 8) * N + col) = pack2bf(v2 - h2, v3 - h3);
            }
        }
    }
}

// ---------------- per-segment attention (qkv fused input, split bf16 output) ----
__global__ void attn_kernel(const float* __restrict__ qkv,
                            bf16* __restrict__ thi, bf16* __restrict__ tlo,
                            int start, int len)
{
    extern __shared__ float sm[];
    int bid = blockIdx.x;
    int hh = bid & 7;
    int b  = bid >> 3;
    int tid = threadIdx.x;        // 256
    int h64 = hh * HD;
    size_t rowbase = (size_t)b * LTOT + start;
    int lenp = len + 4;

    float* sQ  = sm;                       // len*64  (later V)
    float* sKt = sm + len * HD;            // 64*(len+4)
    float* sS  = sKt + HD * lenp;          // len*(len+4)

    for (int e = tid; e < len * HD; e += 256) {
        int l = e >> 6, kk = e & 63;
        size_t gi = (rowbase + l) * QKVS + h64 + kk;
        sQ[e] = qkv[gi];
        sKt[kk * lenp + l] = qkv[gi + 512];
    }
    __syncthreads();

    int nq4 = len >> 2;
    for (int e = tid; e < len * nq4; e += 256) {
        int l  = e / nq4;
        int m4 = (e - l * nq4) * 4;
        const float* qr = sQ + l * HD;
        float ax = 0.0f, ay = 0.0f, az = 0.0f, aw = 0.0f;
        #pragma unroll 8
        for (int kk = 0; kk < HD; kk++) {
            float qv = qr[kk];
            float4 kv = *(const float4*)&sKt[kk * lenp + m4];
            ax += qv * kv.x; ay += qv * kv.y;
            az += qv * kv.z; aw += qv * kv.w;
        }
        float4 rr; rr.x = ax * 0.125f; rr.y = ay * 0.125f;
        rr.z = az * 0.125f; rr.w = aw * 0.125f;
        *(float4*)&sS[l * lenp + m4] = rr;
    }
    __syncthreads();

    for (int e = tid; e < len * HD; e += 256) {
        int l = e >> 6, kk = e & 63;
        sQ[e] = qkv[(rowbase + l) * QKVS + h64 + kk + 1024];
    }
    if (tid < len) {
        float* row = sS + tid * lenp;
        float mx = -1e30f;
        for (int m = 0; m < len; m++) mx = fmaxf(mx, row[m]);
        float sum = 0.0f;
        for (int m = 0; m < len; m++) {
            float ev = expf(row[m] - mx);
            row[m] = ev;
            sum += ev;
        }
        float inv = 1.0f / sum;
        for (int m = 0; m < len; m++) row[m] *= inv;
    }
    __syncthreads();

    for (int e = tid; e < len * (HD / 4); e += 256) {
        int l  = e >> 4;
        int d4 = (e & 15) * 4;
        const float* srow = sS + l * lenp;
        float ax = 0.0f, ay = 0.0f, az = 0.0f, aw = 0.0f;
        #pragma unroll 8
        for (int m = 0; m < len; m++) {
            float s = srow[m];
            float4 vv = *(const float4*)&sQ[m * HD + d4];
            ax += s * vv.x; ay += s * vv.y;
            az += s * vv.z; aw += s * vv.w;
        }
        size_t go = (rowbase + l) * DM + h64 + d4;
        float hx = bfhi(ax), hy = bfhi(ay), hz = bfhi(az), hw = bfhi(aw);
        *(uint2*)(thi + go) = make_uint2(pack2bf(hx, hy), pack2bf(hz, hw));
        *(uint2*)(tlo + go) = make_uint2(pack2bf(ax - hx, ay - hy), pack2bf(az - hz, aw - hw));
    }
}

// ---------------- residual + LayerNorm (+ optional split output) ----------------
__global__ void ln_kernel(const float* __restrict__ x, const float* __restrict__ res,
                          const float* __restrict__ g, const float* __restrict__ bb,
                          float* __restrict__ out,
                          bf16* __restrict__ ohi, bf16* __restrict__ olo,
                          int hasRes)
{
    int row = blockIdx.x;
    int tid = threadIdx.x;   // 128
    float4 vv = ((const float4*)(x + (size_t)row * DM))[tid];
    if (hasRes) {
        float4 rr = ((const float4*)(res + (size_t)row * DM))[tid];
        vv.x += rr.x; vv.y += rr.y; vv.z += rr.z; vv.w += rr.w;
    }
    float sum = vv.x + vv.y + vv.z + vv.w;
    float sq  = vv.x * vv.x + vv.y * vv.y + vv.z * vv.z + vv.w * vv.w;

    #pragma unroll
    for (int off = 16; off; off >>= 1) {
        sum += __shfl_xor_sync(0xFFFFFFFFu, sum, off);
        sq  += __shfl_xor_sync(0xFFFFFFFFu, sq,  off);
    }
    __shared__ float red[2][4];
    int w = tid >> 5;
    if ((tid & 31) == 0) { red[0][w] = sum; red[1][w] = sq; }
    __syncthreads();
    sum = red[0][0] + red[0][1] + red[0][2] + red[0][3];
    sq  = red[1][0] + red[1][1] + red[1][2] + red[1][3];

    float mean = sum * (1.0f / DM);
    float var  = sq * (1.0f / DM) - mean * mean;
    float rstd = rsqrtf(var + 1e-5f);

    float4 gv = ((const float4*)g)[tid];
    float4 bv = ((const float4*)bb)[tid];
    float4 ov;
    ov.x = (vv.x - mean) * rstd * gv.x + bv.x;
    ov.y = (vv.y - mean) * rstd * gv.y + bv.y;
    ov.z = (vv.z - mean) * rstd * gv.z + bv.z;
    ov.w = (vv.w - mean) * rstd * gv.w + bv.w;
    ((float4*)(out + (size_t)row * DM))[tid] = ov;

    if (ohi) {
        float hx = bfhi(ov.x), hy = bfhi(ov.y), hz = bfhi(ov.z), hw = bfhi(ov.w);
        ((uint2*)(ohi + (size_t)row * DM))[tid] =
            make_uint2(pack2bf(hx, hy), pack2bf(hz, hw));
        ((uint2*)(olo + (size_t)row * DM))[tid] =
            make_uint2(pack2bf(ov.x - hx, ov.y - hy), pack2bf(ov.z - hz, ov.w - hw));
    }
}

// ---------------- host launcher ----------------
extern "C" void kernel_launch(void* const* d_in, const int* in_sizes, int n_in,
                              void* d_out, int out_size)
{
    (void)in_sizes; (void)n_in; (void)out_size;
    const float* x_enc = (const float*)d_in[0];
    const float* W_emb = (const float*)d_in[1];
    const float* Wq    = (const float*)d_in[2];
    const float* bq    = (const float*)d_in[3];
    const float* Wk    = (const float*)d_in[4];
    const float* bk    = (const float*)d_in[5];
    const float* Wv    = (const float*)d_in[6];
    const float* bv    = (const float*)d_in[7];
    const float* Wo    = (const float*)d_in[8];
    const float* bo    = (const float*)d_in[9];
    const float* ln1_g = (const float*)d_in[10];
    const float* ln1_b = (const float*)d_in[11];
    const float* W1    = (const float*)d_in[12];
    const float* b1    = (const float*)d_in[13];
    const float* W2    = (const float*)d_in[14];
    const float* b2    = (const float*)d_in[15];
    const float* ln2_g = (const float*)d_in[16];
    const float* ln2_b = (const float*)d_in[17];
    const float* lnf_g = (const float*)d_in[18];
    const float* lnf_b = (const float*)d_in[19];

    float *h, *ob, *qkv, *bqkv;
    bf16 *hhi, *hlo, *thi, *tlo, *fhi, *flo, *whi, *wlo;
    cudaGetSymbolAddress((void**)&h,    g_h);
    cudaGetSymbolAddress((void**)&ob,   g_o);
    cudaGetSymbolAddress((void**)&qkv,  g_qkv);
    cudaGetSymbolAddress((void**)&bqkv, g_bqkv);
    cudaGetSymbolAddress((void**)&hhi,  g_hhi);
    cudaGetSymbolAddress((void**)&hlo,  g_hlo);
    cudaGetSymbolAddress((void**)&thi,  g_thi);
    cudaGetSymbolAddress((void**)&tlo,  g_tlo);
    cudaGetSymbolAddress((void**)&fhi,  g_fhi);
    cudaGetSymbolAddress((void**)&flo,  g_flo);
    cudaGetSymbolAddress((void**)&whi,  g_whi);
    cudaGetSymbolAddress((void**)&wlo,  g_wlo);

    cudaFuncSetAttribute(attn_kernel, cudaFuncAttributeMaxDynamicSharedMemorySize, 140000);
    cudaFuncSetAttribute(gemm_mma, cudaFuncAttributeMaxDynamicSharedMemorySize, GSMEM);

    // split-weight layout:
    //  [0, 3*512*1536)               : fused QKV per layer ([L][512][1536])
    //  OO .. +3*WD                   : Wo
    //  O1 .. +3*WF                   : W1
    //  O2 .. +3*WF                   : W2
    const size_t WD = (size_t)DM * DM;          // 262144
    const size_t WF = (size_t)DM * DFF;         // 1048576
    const size_t WQKV = (size_t)NLAYERS * 512 * QKVS;   // 2359296
    const size_t OO = WQKV, O1 = OO + 3 * WD, O2 = O1 + 3 * WF;

    wsplit_qkv<<<(int)(WQKV / 4 + 255) / 256, 256>>>(Wq, Wk, Wv, whi, wlo);
    packbias_kernel<<<(NLAYERS * QKVS + 255) / 256, 256>>>(bq, bk, bv, bqkv);
    wsplit_kernel<<<(int)(3 * WD / 4 + 255) / 256, 256>>>(Wo, whi + OO, wlo + OO, (int)(3 * WD / 4));
    wsplit_kernel<<<(int)(3 * WF / 4 + 255) / 256, 256>>>(W1, whi + O1, wlo + O1, (int)(3 * WF / 4));
    wsplit_kernel<<<(int)(3 * WF / 4 + 255) / 256, 256>>>(W2, whi + O2, wlo + O2, (int)(3 * WF / 4));

    embed_kernel<<<dim3(LTOT, BSEQ), 256>>>(x_enc, W_emb, h, hhi, hlo);

    const int segStart[4] = {0, 16, 48, 112};
    const int segLen[4]   = {16, 32, 64, 128};

    dim3 gQKV(QKVS / 128, MROWS / 128);  // (12, 480)
    dim3 gD(DM / 128, MROWS / 128);      // (4, 480)
    dim3 gF(DFF / 128, MROWS / 128);     // (16, 480)

    for (int i = 0; i < NLAYERS; i++) {
        gemm_mma<<<gQKV, 128, GSMEM>>>(hhi, hlo,
                                       whi + (size_t)i * 512 * QKVS, wlo + (size_t)i * 512 * QKVS,
                                       bqkv + i * QKVS, qkv, nullptr, nullptr,
                                       MROWS, QKVS, DM, 0);

        for (int s = 0; s < 4; s++) {
            int len = segLen[s];
            int lenp = len + 4;
            size_t smem = (size_t)(len * HD + HD * lenp + len * lenp) * sizeof(float);
            attn_kernel<<<BSEQ * NHEADS, 256, smem>>>(qkv, thi, tlo, segStart[s], len);
        }

        gemm_mma<<<gD, 128, GSMEM>>>(thi, tlo, whi + OO + i * WD, wlo + OO + i * WD,
                                     bo + i * DM, ob, nullptr, nullptr, MROWS, DM, DM, 0);
        ln_kernel<<<MROWS, 128>>>(h, ob, ln1_g + i * DM, ln1_b + i * DM, h, hhi, hlo, 1);

        gemm_mma<<<gF, 128, GSMEM>>>(hhi, hlo, whi + O1 + i * WF, wlo + O1 + i * WF,
                                     b1 + i * DFF, nullptr, fhi, flo, MROWS, DFF, DM, 1);
        gemm_mma<<<gD, 128, GSMEM>>>(fhi, flo, whi + O2 + i * WF, wlo + O2 + i * WF,
                                     b2 + i * DM, ob, nullptr, nullptr, MROWS, DM, DFF, 0);
        ln_kernel<<<MROWS, 128>>>(h, ob, ln2_g + i * DM, ln2_b + i * DM, h, hhi, hlo, 1);
    }

    ln_kernel<<<MROWS, 128>>>(h, nullptr, lnf_g, lnf_b, (float*)d_out, nullptr, nullptr, 0);
}

// round 13
// speedup vs baseline: 2.1413x; 1.7073x over previous
#include <cuda_runtime.h>
#include <cuda_fp16.h>
#include <cstdint>

#define BS       8
#define CCH      32
#define TLEN     2048
#define PATCH_N  16
#define DM       512
#define NHEADS   8
#define HD       64
#define DFF      2048
#define NLAYERS  3
#define BSEQ     (BS * CCH)       // 256
#define LTOT     240
#define MROWS    (BSEQ * LTOT)    // 61440
#define QKVS     1536

// ---------------- scratch ----------------
__device__ float  g_h  [MROWS * DM];
__device__ float  g_o  [MROWS * DM];
__device__ float  g_qkv[(size_t)MROWS * QKVS];
__device__ float  g_bqkv[NLAYERS * QKVS];
__device__ __half g_hh [MROWS * DM];               // h in fp16 (GEMM input)
__device__ __half g_th [MROWS * DM];               // attention out fp16
__device__ __half g_fh [(size_t)MROWS * DFF];      // FFN1 out fp16
#define WTOT 9437184
__device__ __half g_wh [WTOT];

// ---------------- helpers ----------------
__device__ __forceinline__ uint32_t smem_u32(const void* p) {
    uint32_t a;
    asm("{ .reg .u64 t; cvta.to.shared.u64 t, %1; cvt.u32.u64 %0, t; }"
        : "=r"(a) : "l"(p));
    return a;
}
__device__ __forceinline__ void cpasync16(uint32_t d, const void* s) {
    asm volatile("cp.async.cg.shared.global [%0], [%1], 16;"
                 :: "r"(d), "l"(s) : "memory");
}
__device__ __forceinline__ float gelu_tanh(float x) {
    float x3 = x * x * x;
    float t = tanhf(0.7978845608028654f * (x + 0.044715f * x3));
    return 0.5f * x * (1.0f + t);
}
__device__ __forceinline__ uint32_t pack2h(float x, float y) {
    __half2 h = __floats2half2_rn(x, y);
    return *reinterpret_cast<uint32_t*>(&h);
}

#define LDSM_X4(r0, r1, r2, r3, addr) \
    asm volatile("ldmatrix.sync.aligned.m8n8.x4.shared.b16 {%0,%1,%2,%3}, [%4];" \
                 : "=r"(r0), "=r"(r1), "=r"(r2), "=r"(r3) : "r"(addr))

#define LDSM_X4_T(r0, r1, r2, r3, addr) \
    asm volatile("ldmatrix.sync.aligned.m8n8.x4.trans.shared.b16 {%0,%1,%2,%3}, [%4];" \
                 : "=r"(r0), "=r"(r1), "=r"(r2), "=r"(r3) : "r"(addr))

#define MMA_F16(d, a, b0v, b1v) \
    asm volatile("mma.sync.aligned.m16n8k16.row.col.f32.f16.f16.f32 " \
                 "{%0,%1,%2,%3}, {%4,%5,%6,%7}, {%8,%9}, {%0,%1,%2,%3};" \
                 : "+f"((d)[0]), "+f"((d)[1]), "+f"((d)[2]), "+f"((d)[3]) \
                 : "r"((a)[0]), "r"((a)[1]), "r"((a)[2]), "r"((a)[3]), \
                   "r"(b0v), "r"(b1v))

// ---------------- weight conversion ----------------
__global__ void wconv_kernel(const float* __restrict__ w, __half* __restrict__ o, int n4)
{
    int i = blockIdx.x * 256 + threadIdx.x;
    if (i >= n4) return;
    float4 v = ((const float4*)w)[i];
    ((uint2*)o)[i] = make_uint2(pack2h(v.x, v.y), pack2h(v.z, v.w));
}

// combined Wq|Wk|Wv -> [L][512][1536] fp16
__global__ void wconv_qkv(const float* __restrict__ Wq, const float* __restrict__ Wk,
                          const float* __restrict__ Wv, __half* __restrict__ o)
{
    int i = blockIdx.x * 256 + threadIdx.x;
    if (i >= NLAYERS * 512 * (QKVS / 4)) return;
    int c4 = i % (QKVS / 4);
    int rem = i / (QKVS / 4);
    int k = rem % 512, L = rem / 512;
    int c = c4 * 4;
    const float* src;
    if (c < 512)        src = Wq + ((size_t)L * 512 + k) * 512 + c;
    else if (c < 1024)  src = Wk + ((size_t)L * 512 + k) * 512 + (c - 512);
    else                src = Wv + ((size_t)L * 512 + k) * 512 + (c - 1024);
    float4 v = *(const float4*)src;
    ((uint2*)o)[i] = make_uint2(pack2h(v.x, v.y), pack2h(v.z, v.w));
}

__global__ void packbias_kernel(const float* __restrict__ bq, const float* __restrict__ bk,
                                const float* __restrict__ bv, float* __restrict__ out)
{
    int i = blockIdx.x * 256 + threadIdx.x;
    if (i >= NLAYERS * QKVS) return;
    int L = i / QKVS, c = i % QKVS;
    float v = (c < 512) ? bq[L * 512 + c]
            : (c < 1024) ? bk[L * 512 + c - 512]
                         : bv[L * 512 + c - 1024];
    out[i] = v;
}

// ---------------- embedding ----------------
__global__ void embed_kernel(const float* __restrict__ x_enc,
                             const float* __restrict__ Wemb,
                             float* __restrict__ h, __half* __restrict__ hh)
{
    int tok = blockIdx.x;
    int r   = blockIdx.y;
    int tid = threadIdx.x;
    int b  = r >> 5;
    int cc = r & 31;

    int kstr, j;
    if (tok < 16)       { kstr = 8; j = tok; }
    else if (tok < 48)  { kstr = 4; j = tok - 16; }
    else if (tok < 112) { kstr = 2; j = tok - 48; }
    else                { kstr = 1; j = tok - 112; }

    __shared__ float xv[PATCH_N];
    if (tid < PATCH_N) {
        int tt = kstr * (j * PATCH_N + tid);
        xv[tid] = x_enc[((size_t)b * TLEN + tt) * CCH + cc];
    }
    __syncthreads();

    float pepos = (float)(j * kstr);
    const float cln = 9.210340371976184f / (float)DM;

    for (int d = tid; d < DM; d += 256) {
        float acc = 0.0f;
        #pragma unroll
        for (int p = 0; p < PATCH_N; p++)
            acc += xv[p] * Wemb[p * DM + d];
        int i2 = d & ~1;
        float ang = pepos * __expf(-(float)i2 * cln);
        float pv = (d & 1) ? cosf(ang) : sinf(ang);
        float val = acc + pv;
        size_t gi = ((size_t)r * LTOT + tok) * DM + d;
        h[gi] = val;
        hh[gi] = __float2half_rn(val);
    }
}

// ---------------- fp16 mma.sync GEMM, 4 warps 64x64, 4-stage cp.async ----------------
#define AST 40          // A smem row stride (halves): 32 + 8 pad -> 80B
#define BST 136         // B smem row stride (halves): 128 + 8 pad -> 272B
#define ST_A 0
#define ST_B 10240      // bytes (128*40*2)
#define STAGEB 18944    // 10240 + 32*136*2
#define NSTG 4
#define GSMEM (NSTG * STAGEB)   // 75776

__global__ __launch_bounds__(128, 2)
void gemm_mma(const __half* __restrict__ A, const __half* __restrict__ Bm,
              const float* __restrict__ bias,
              float* __restrict__ C, __half* __restrict__ Ch,
              int M, int N, int K, int doGelu)
{
    extern __shared__ char dsm[];
    uint32_t dynb = smem_u32(dsm);

    int tid  = threadIdx.x;
    int wid  = tid >> 5;    // 0..3
    int lane = tid & 31;
    int wm = wid & 1;       // 2 row groups of 64
    int wn = wid >> 1;      // 2 col groups of 64
    int m0 = blockIdx.y * 128;
    int n0 = blockIdx.x * 128;

    float acc[4][8][4];
    #pragma unroll
    for (int i = 0; i < 4; i++)
        #pragma unroll
        for (int j = 0; j < 8; j++)
            #pragma unroll
            for (int c = 0; c < 4; c++) acc[i][j][c] = 0.0f;

    uint32_t aoffL = ((uint32_t)((wm * 64 + (lane & 15)) * AST + (lane >> 4) * 8)) * 2;
    uint32_t boffL = ((uint32_t)(((lane & 7) + ((lane >> 3) & 1) * 8) * BST
                                 + wn * 64 + (lane >> 4) * 8)) * 2;

    int nslab = K >> 5;

    auto issue = [&](int j) {
        uint32_t sb = dynb + (uint32_t)(j % NSTG) * STAGEB;
        int k0 = j * 32;
        #pragma unroll
        for (int i = 0; i < 4; i++) {
            int chunk = i * 128 + tid;
            int row = chunk >> 2, c8 = (chunk & 3) * 8;
            uint32_t off = (uint32_t)(row * AST + c8) * 2;
            cpasync16(sb + ST_A + off, A + (size_t)(m0 + row) * K + k0 + c8);
        }
        #pragma unroll
        for (int i = 0; i < 4; i++) {
            int chunk = i * 128 + tid;
            int row = chunk >> 4, c8 = (chunk & 15) * 8;
            uint32_t off = (uint32_t)(row * BST + c8) * 2;
            cpasync16(sb + ST_B + off, Bm + (size_t)(k0 + row) * N + n0 + c8);
        }
        asm volatile("cp.async.commit_group;" ::: "memory");
    };

    issue(0); issue(1); issue(2);
    for (int j = 0; j < nslab; j++) {
        if (j < nslab - 2)
            asm volatile("cp.async.wait_group 2;" ::: "memory");
        else if (j == nslab - 2)
            asm volatile("cp.async.wait_group 1;" ::: "memory");
        else
            asm volatile("cp.async.wait_group 0;" ::: "memory");
        __syncthreads();

        uint32_t sb = dynb + (uint32_t)(j % NSTG) * STAGEB;
        uint32_t aB = sb + ST_A, bB = sb + ST_B;

        // safe: buffer (j+3)%NSTG last read in iter j-1; all threads passed barrier
        if (j + 3 < nslab) issue(j + 3);

        #pragma unroll
        for (int ks = 0; ks < 2; ks++) {
            uint32_t kbA = (uint32_t)(ks * 16) * 2;
            uint32_t kbB = (uint32_t)(ks * 16 * BST) * 2;

            uint32_t ah[4][4];
            #pragma unroll
            for (int mf = 0; mf < 4; mf++) {
                uint32_t off = aoffL + (uint32_t)(mf * 16 * AST) * 2 + kbA;
                LDSM_X4(ah[mf][0], ah[mf][1], ah[mf][2], ah[mf][3], aB + off);
            }
            uint32_t bh[16];
            #pragma unroll
            for (int nb = 0; nb < 4; nb++) {
                uint32_t off = boffL + (uint32_t)(nb * 16) * 2 + kbB;
                LDSM_X4_T(bh[nb * 4 + 0], bh[nb * 4 + 1], bh[nb * 4 + 2], bh[nb * 4 + 3], bB + off);
            }

            #pragma unroll
            for (int mf = 0; mf < 4; mf++)
                #pragma unroll
                for (int nf = 0; nf < 8; nf++)
                    MMA_F16(acc[mf][nf], ah[mf], bh[nf * 2], bh[nf * 2 + 1]);
        }
    }

    // epilogue
    int rbase = m0 + wm * 64 + (lane >> 2);
    int cbase = n0 + wn * 64 + (lane & 3) * 2;
    #pragma unroll
    for (int mf = 0; mf < 4; mf++) {
        #pragma unroll
        for (int nf = 0; nf < 8; nf++) {
            int col = cbase + nf * 8;
            float b0v = bias[col], b1v = bias[col + 1];
            float v0 = acc[mf][nf][0] + b0v;
            float v1 = acc[mf][nf][1] + b1v;
            float v2 = acc[mf][nf][2] + b0v;
            float v3 = acc[mf][nf][3] + b1v;
            if (doGelu) {
                v0 = gelu_tanh(v0); v1 = gelu_tanh(v1);
                v2 = gelu_tanh(v2); v3 = gelu_tanh(v3);
            }
            int r0 = rbase + mf * 16;
            if (C) {
                *(float2*)(C + (size_t)r0 * N + col)       = make_float2(v0, v1);
                *(float2*)(C + (size_t)(r0 + 8) * N + col) = make_float2(v2, v3);
            }
            if (Ch) {
                *(uint32_t*)(Ch + (size_t)r0 * N + col)       = pack2h(v0, v1);
                *(uint32_t*)(Ch + (size_t)(r0 + 8) * N + col) = pack2h(v2, v3);
            }
        }
    }
}

// ---------------- per-segment attention (qkv fused fp32 input, fp16 output) ----
__global__ void attn_kernel(const float* __restrict__ qkv,
                            __half* __restrict__ th,
                            int start, int len)
{
    extern __shared__ float sm[];
    int bid = blockIdx.x;
    int hh = bid & 7;
    int b  = bid >> 3;
    int tid = threadIdx.x;        // 256
    int h64 = hh * HD;
    size_t rowbase = (size_t)b * LTOT + start;
    int lenp = len + 4;

    float* sQ  = sm;                       // len*64  (later V)
    float* sKt = sm + len * HD;            // 64*(len+4)
    float* sS  = sKt + HD * lenp;          // len*(len+4)

    for (int e = tid; e < len * HD; e += 256) {
        int l = e >> 6, kk = e & 63;
        size_t gi = (rowbase + l) * QKVS + h64 + kk;
        sQ[e] = qkv[gi];
        sKt[kk * lenp + l] = qkv[gi + 512];
    }
    __syncthreads();

    int nq4 = len >> 2;
    for (int e = tid; e < len * nq4; e += 256) {
        int l  = e / nq4;
        int m4 = (e - l * nq4) * 4;
        const float* qr = sQ + l * HD;
        float ax = 0.0f, ay = 0.0f, az = 0.0f, aw = 0.0f;
        #pragma unroll 8
        for (int kk = 0; kk < HD; kk++) {
            float qv = qr[kk];
            float4 kv = *(const float4*)&sKt[kk * lenp + m4];
            ax += qv * kv.x; ay += qv * kv.y;
            az += qv * kv.z; aw += qv * kv.w;
        }
        float4 rr; rr.x = ax * 0.125f; rr.y = ay * 0.125f;
        rr.z = az * 0.125f; rr.w = aw * 0.125f;
        *(float4*)&sS[l * lenp + m4] = rr;
    }
    __syncthreads();

    for (int e = tid; e < len * HD; e += 256) {
        int l = e >> 6, kk = e & 63;
        sQ[e] = qkv[(rowbase + l) * QKVS + h64 + kk + 1024];
    }
    if (tid < len) {
        float* row = sS + tid * lenp;
        float mx = -1e30f;
        for (int m = 0; m < len; m++) mx = fmaxf(mx, row[m]);
        float sum = 0.0f;
        for (int m = 0; m < len; m++) {
            float ev = expf(row[m] - mx);
            row[m] = ev;
            sum += ev;
        }
        float inv = 1.0f / sum;
        for (int m = 0; m < len; m++) row[m] *= inv;
    }
    __syncthreads();

    for (int e = tid; e < len * (HD / 4); e += 256) {
        int l  = e >> 4;
        int d4 = (e & 15) * 4;
        const float* srow = sS + l * lenp;
        float ax = 0.0f, ay = 0.0f, az = 0.0f, aw = 0.0f;
        #pragma unroll 8
        for (int m = 0; m < len; m++) {
            float s = srow[m];
            float4 vv = *(const float4*)&sQ[m * HD + d4];
            ax += s * vv.x; ay += s * vv.y;
            az += s * vv.z; aw += s * vv.w;
        }
        size_t go = (rowbase + l) * DM + h64 + d4;
        *(uint2*)(th + go) = make_uint2(pack2h(ax, ay), pack2h(az, aw));
    }
}

// ---------------- residual + LayerNorm (+ optional fp16 output) ----------------
__global__ void ln_kernel(const float* __restrict__ x, const float* __restrict__ res,
                          const float* __restrict__ g, const float* __restrict__ bb,
                          float* __restrict__ out, __half* __restrict__ oh,
                          int hasRes)
{
    int row = blockIdx.x;
    int tid = threadIdx.x;   // 128
    float4 vv = ((const float4*)(x + (size_t)row * DM))[tid];
    if (hasRes) {
        float4 rr = ((const float4*)(res + (size_t)row * DM))[tid];
        vv.x += rr.x; vv.y += rr.y; vv.z += rr.z; vv.w += rr.w;
    }
    float sum = vv.x + vv.y + vv.z + vv.w;
    float sq  = vv.x * vv.x + vv.y * vv.y + vv.z * vv.z + vv.w * vv.w;

    #pragma unroll
    for (int off = 16; off; off >>= 1) {
        sum += __shfl_xor_sync(0xFFFFFFFFu, sum, off);
        sq  += __shfl_xor_sync(0xFFFFFFFFu, sq,  off);
    }
    __shared__ float red[2][4];
    int w = tid >> 5;
    if ((tid & 31) == 0) { red[0][w] = sum; red[1][w] = sq; }
    __syncthreads();
    sum = red[0][0] + red[0][1] + red[0][2] + red[0][3];
    sq  = red[1][0] + red[1][1] + red[1][2] + red[1][3];

    float mean = sum * (1.0f / DM);
    float var  = sq * (1.0f / DM) - mean * mean;
    float rstd = rsqrtf(var + 1e-5f);

    float4 gv = ((const float4*)g)[tid];
    float4 bv = ((const float4*)bb)[tid];
    float4 ov;
    ov.x = (vv.x - mean) * rstd * gv.x + bv.x;
    ov.y = (vv.y - mean) * rstd * gv.y + bv.y;
    ov.z = (vv.z - mean) * rstd * gv.z + bv.z;
    ov.w = (vv.w - mean) * rstd * gv.w + bv.w;
    ((float4*)(out + (size_t)row * DM))[tid] = ov;

    if (oh) {
        ((uint2*)(oh + (size_t)row * DM))[tid] =
            make_uint2(pack2h(ov.x, ov.y), pack2h(ov.z, ov.w));
    }
}

// ---------------- host launcher ----------------
extern "C" void kernel_launch(void* const* d_in, const int* in_sizes, int n_in,
                              void* d_out, int out_size)
{
    (void)in_sizes; (void)n_in; (void)out_size;
    const float* x_enc = (const float*)d_in[0];
    const float* W_emb = (const float*)d_in[1];
    const float* Wq    = (const float*)d_in[2];
    const float* bq    = (const float*)d_in[3];
    const float* Wk    = (const float*)d_in[4];
    const float* bk    = (const float*)d_in[5];
    const float* Wv    = (const float*)d_in[6];
    const float* bv    = (const float*)d_in[7];
    const float* Wo    = (const float*)d_in[8];
    const float* bo    = (const float*)d_in[9];
    const float* ln1_g = (const float*)d_in[10];
    const float* ln1_b = (const float*)d_in[11];
    const float* W1    = (const float*)d_in[12];
    const float* b1    = (const float*)d_in[13];
    const float* W2    = (const float*)d_in[14];
    const float* b2    = (const float*)d_in[15];
    const float* ln2_g = (const float*)d_in[16];
    const float* ln2_b = (const float*)d_in[17];
    const float* lnf_g = (const float*)d_in[18];
    const float* lnf_b = (const float*)d_in[19];

    float *h, *ob, *qkv, *bqkv;
    __half *hh, *th, *fh, *wh;
    cudaGetSymbolAddress((void**)&h,    g_h);
    cudaGetSymbolAddress((void**)&ob,   g_o);
    cudaGetSymbolAddress((void**)&qkv,  g_qkv);
    cudaGetSymbolAddress((void**)&bqkv, g_bqkv);
    cudaGetSymbolAddress((void**)&hh,   g_hh);
    cudaGetSymbolAddress((void**)&th,   g_th);
    cudaGetSymbolAddress((void**)&fh,   g_fh);
    cudaGetSymbolAddress((void**)&wh,   g_wh);

    cudaFuncSetAttribute(attn_kernel, cudaFuncAttributeMaxDynamicSharedMemorySize, 140000);
    cudaFuncSetAttribute(gemm_mma, cudaFuncAttributeMaxDynamicSharedMemorySize, GSMEM);

    // fp16-weight layout:
    //  [0, WQKV)      : fused QKV per layer ([L][512][1536])
    //  OO .. +3*WD    : Wo ;  O1 .. +3*WF : W1 ;  O2 .. +3*WF : W2
    const size_t WD = (size_t)DM * DM;
    const size_t WF = (size_t)DM * DFF;
    const size_t WQKV = (size_t)NLAYERS * 512 * QKVS;
    const size_t OO = WQKV, O1 = OO + 3 * WD, O2 = O1 + 3 * WF;

    wconv_qkv<<<(int)(WQKV / 4 + 255) / 256, 256>>>(Wq, Wk, Wv, wh);
    packbias_kernel<<<(NLAYERS * QKVS + 255) / 256, 256>>>(bq, bk, bv, bqkv);
    wconv_kernel<<<(int)(3 * WD / 4 + 255) / 256, 256>>>(Wo, wh + OO, (int)(3 * WD / 4));
    wconv_kernel<<<(int)(3 * WF / 4 + 255) / 256, 256>>>(W1, wh + O1, (int)(3 * WF / 4));
    wconv_kernel<<<(int)(3 * WF / 4 + 255) / 256, 256>>>(W2, wh + O2, (int)(3 * WF / 4));

    embed_kernel<<<dim3(LTOT, BSEQ), 256>>>(x_enc, W_emb, h, hh);

    const int segStart[4] = {0, 16, 48, 112};
    const int segLen[4]   = {16, 32, 64, 128};

    dim3 gQKV(QKVS / 128, MROWS / 128);  // (12, 480)
    dim3 gD(DM / 128, MROWS / 128);      // (4, 480)
    dim3 gF(DFF / 128, MROWS / 128);     // (16, 480)

    for (int i = 0; i < NLAYERS; i++) {
        gemm_mma<<<gQKV, 128, GSMEM>>>(hh, wh + (size_t)i * 512 * QKVS,
                                       bqkv + i * QKVS, qkv, nullptr,
                                       MROWS, QKVS, DM, 0);

        for (int s = 0; s < 4; s++) {
            int len = segLen[s];
            int lenp = len + 4;
            size_t smem = (size_t)(len * HD + HD * lenp + len * lenp) * sizeof(float);
            attn_kernel<<<BSEQ * NHEADS, 256, smem>>>(qkv, th, segStart[s], len);
        }

        gemm_mma<<<gD, 128, GSMEM>>>(th, wh + OO + i * WD,
                                     bo + i * DM, ob, nullptr, MROWS, DM, DM, 0);
        ln_kernel<<<MROWS, 128>>>(h, ob, ln1_g + i * DM, ln1_b + i * DM, h, hh, 1);

        gemm_mma<<<gF, 128, GSMEM>>>(hh, wh + O1 + i * WF,
                                     b1 + i * DFF, nullptr, fh, MROWS, DFF, DM, 1);
        gemm_mma<<<gD, 128, GSMEM>>>(fh, wh + O2 + i * WF,
                                     b2 + i * DM, ob, nullptr, MROWS, DM, DFF, 0);
        ln_kernel<<<MROWS, 128>>>(h, ob, ln2_g + i * DM, ln2_b + i * DM, h, hh, 1);
    }

    ln_kernel<<<MROWS, 128>>>(h, nullptr, lnf_g, lnf_b, (float*)d_out, nullptr, 0);
}

// round 14
// speedup vs baseline: 2.9564x; 1.3806x over previous
#include <cuda_runtime.h>
#include <cuda_fp16.h>
#include <cstdint>

#define BS       8
#define CCH      32
#define TLEN     2048
#define PATCH_N  16
#define DM       512
#define NHEADS   8
#define HD       64
#define DFF      2048
#define NLAYERS  3
#define BSEQ     (BS * CCH)       // 256
#define LTOT     240
#define MROWS    (BSEQ * LTOT)    // 61440
#define QKVS     1536

// ---------------- scratch ----------------
__device__ float  g_h  [MROWS * DM];
__device__ float  g_o  [MROWS * DM];
__device__ float  g_bqkv[NLAYERS * QKVS];
__device__ __half g_qkvh[(size_t)MROWS * QKVS];    // fused QKV fp16
__device__ __half g_hh [MROWS * DM];               // h in fp16 (GEMM input)
__device__ __half g_th [MROWS * DM];               // attention out fp16
__device__ __half g_fh [(size_t)MROWS * DFF];      // FFN1 out fp16
#define WTOT 9437184
__device__ __half g_wh [WTOT];

// ---------------- helpers ----------------
__device__ __forceinline__ uint32_t smem_u32(const void* p) {
    uint32_t a;
    asm("{ .reg .u64 t; cvta.to.shared.u64 t, %1; cvt.u32.u64 %0, t; }"
        : "=r"(a) : "l"(p));
    return a;
}
__device__ __forceinline__ void cpasync16(uint32_t d, const void* s) {
    asm volatile("cp.async.cg.shared.global [%0], [%1], 16;"
                 :: "r"(d), "l"(s) : "memory");
}
__device__ __forceinline__ float gelu_tanh(float x) {
    float x3 = x * x * x;
    float t = tanhf(0.7978845608028654f * (x + 0.044715f * x3));
    return 0.5f * x * (1.0f + t);
}
__device__ __forceinline__ uint32_t pack2h(float x, float y) {
    __half2 h = __floats2half2_rn(x, y);
    return *reinterpret_cast<uint32_t*>(&h);
}

#define LDSM_X4(r0, r1, r2, r3, addr) \
    asm volatile("ldmatrix.sync.aligned.m8n8.x4.shared.b16 {%0,%1,%2,%3}, [%4];" \
                 : "=r"(r0), "=r"(r1), "=r"(r2), "=r"(r3) : "r"(addr))

#define LDSM_X4_T(r0, r1, r2, r3, addr) \
    asm volatile("ldmatrix.sync.aligned.m8n8.x4.trans.shared.b16 {%0,%1,%2,%3}, [%4];" \
                 : "=r"(r0), "=r"(r1), "=r"(r2), "=r"(r3) : "r"(addr))

#define MMA_F16(d, a, b0v, b1v) \
    asm volatile("mma.sync.aligned.m16n8k16.row.col.f32.f16.f16.f32 " \
                 "{%0,%1,%2,%3}, {%4,%5,%6,%7}, {%8,%9}, {%0,%1,%2,%3};" \
                 : "+f"((d)[0]), "+f"((d)[1]), "+f"((d)[2]), "+f"((d)[3]) \
                 : "r"((a)[0]), "r"((a)[1]), "r"((a)[2]), "r"((a)[3]), \
                   "r"(b0v), "r"(b1v))

// ---------------- weight conversion ----------------
__global__ void wconv_kernel(const float* __restrict__ w, __half* __restrict__ o, int n4)
{
    int i = blockIdx.x * 256 + threadIdx.x;
    if (i >= n4) return;
    float4 v = ((const float4*)w)[i];
    ((uint2*)o)[i] = make_uint2(pack2h(v.x, v.y), pack2h(v.z, v.w));
}

__global__ void wconv_qkv(const float* __restrict__ Wq, const float* __restrict__ Wk,
                          const float* __restrict__ Wv, __half* __restrict__ o)
{
    int i = blockIdx.x * 256 + threadIdx.x;
    if (i >= NLAYERS * 512 * (QKVS / 4)) return;
    int c4 = i % (QKVS / 4);
    int rem = i / (QKVS / 4);
    int k = rem % 512, L = rem / 512;
    int c = c4 * 4;
    const float* src;
    if (c < 512)        src = Wq + ((size_t)L * 512 + k) * 512 + c;
    else if (c < 1024)  src = Wk + ((size_t)L * 512 + k) * 512 + (c - 512);
    else                src = Wv + ((size_t)L * 512 + k) * 512 + (c - 1024);
    float4 v = *(const float4*)src;
    ((uint2*)o)[i] = make_uint2(pack2h(v.x, v.y), pack2h(v.z, v.w));
}

__global__ void packbias_kernel(const float* __restrict__ bq, const float* __restrict__ bk,
                                const float* __restrict__ bv, float* __restrict__ out)
{
    int i = blockIdx.x * 256 + threadIdx.x;
    if (i >= NLAYERS * QKVS) return;
    int L = i / QKVS, c = i % QKVS;
    float v = (c < 512) ? bq[L * 512 + c]
            : (c < 1024) ? bk[L * 512 + c - 512]
                         : bv[L * 512 + c - 1024];
    out[i] = v;
}

// ---------------- embedding ----------------
__global__ void embed_kernel(const float* __restrict__ x_enc,
                             const float* __restrict__ Wemb,
                             float* __restrict__ h, __half* __restrict__ hh)
{
    int tok = blockIdx.x;
    int r   = blockIdx.y;
    int tid = threadIdx.x;
    int b  = r >> 5;
    int cc = r & 31;

    int kstr, j;
    if (tok < 16)       { kstr = 8; j = tok; }
    else if (tok < 48)  { kstr = 4; j = tok - 16; }
    else if (tok < 112) { kstr = 2; j = tok - 48; }
    else                { kstr = 1; j = tok - 112; }

    __shared__ float xv[PATCH_N];
    if (tid < PATCH_N) {
        int tt = kstr * (j * PATCH_N + tid);
        xv[tid] = x_enc[((size_t)b * TLEN + tt) * CCH + cc];
    }
    __syncthreads();

    float pepos = (float)(j * kstr);
    const float cln = 9.210340371976184f / (float)DM;

    for (int d = tid; d < DM; d += 256) {
        float acc = 0.0f;
        #pragma unroll
        for (int p = 0; p < PATCH_N; p++)
            acc += xv[p] * Wemb[p * DM + d];
        int i2 = d & ~1;
        float ang = pepos * __expf(-(float)i2 * cln);
        float pv = (d & 1) ? cosf(ang) : sinf(ang);
        float val = acc + pv;
        size_t gi = ((size_t)r * LTOT + tok) * DM + d;
        h[gi] = val;
        hh[gi] = __float2half_rn(val);
    }
}

// ---------------- fp16 mma.sync GEMM, 4 warps 64x64, 4-stage cp.async ----------------
#define AST 40
#define BST 136
#define ST_A 0
#define ST_B 10240
#define STAGEB 18944
#define NSTG 4
#define GSMEM (NSTG * STAGEB)

__global__ __launch_bounds__(128, 2)
void gemm_mma(const __half* __restrict__ A, const __half* __restrict__ Bm,
              const float* __restrict__ bias,
              float* __restrict__ C, __half* __restrict__ Ch,
              int M, int N, int K, int doGelu)
{
    extern __shared__ char dsm[];
    uint32_t dynb = smem_u32(dsm);

    int tid  = threadIdx.x;
    int wid  = tid >> 5;
    int lane = tid & 31;
    int wm = wid & 1;
    int wn = wid >> 1;
    int m0 = blockIdx.y * 128;
    int n0 = blockIdx.x * 128;

    float acc[4][8][4];
    #pragma unroll
    for (int i = 0; i < 4; i++)
        #pragma unroll
        for (int j = 0; j < 8; j++)
            #pragma unroll
            for (int c = 0; c < 4; c++) acc[i][j][c] = 0.0f;

    uint32_t aoffL = ((uint32_t)((wm * 64 + (lane & 15)) * AST + (lane >> 4) * 8)) * 2;
    uint32_t boffL = ((uint32_t)(((lane & 7) + ((lane >> 3) & 1) * 8) * BST
                                 + wn * 64 + (lane >> 4) * 8)) * 2;

    int nslab = K >> 5;

    auto issue = [&](int j) {
        uint32_t sb = dynb + (uint32_t)(j % NSTG) * STAGEB;
        int k0 = j * 32;
        #pragma unroll
        for (int i = 0; i < 4; i++) {
            int chunk = i * 128 + tid;
            int row = chunk >> 2, c8 = (chunk & 3) * 8;
            uint32_t off = (uint32_t)(row * AST + c8) * 2;
            cpasync16(sb + ST_A + off, A + (size_t)(m0 + row) * K + k0 + c8);
        }
        #pragma unroll
        for (int i = 0; i < 4; i++) {
            int chunk = i * 128 + tid;
            int row = chunk >> 4, c8 = (chunk & 15) * 8;
            uint32_t off = (uint32_t)(row * BST + c8) * 2;
            cpasync16(sb + ST_B + off, Bm + (size_t)(k0 + row) * N + n0 + c8);
        }
        asm volatile("cp.async.commit_group;" ::: "memory");
    };

    issue(0); issue(1); issue(2);
    for (int j = 0; j < nslab; j++) {
        if (j < nslab - 2)
            asm volatile("cp.async.wait_group 2;" ::: "memory");
        else if (j == nslab - 2)
            asm volatile("cp.async.wait_group 1;" ::: "memory");
        else
            asm volatile("cp.async.wait_group 0;" ::: "memory");
        __syncthreads();

        uint32_t sb = dynb + (uint32_t)(j % NSTG) * STAGEB;
        uint32_t aB = sb + ST_A, bB = sb + ST_B;

        if (j + 3 < nslab) issue(j + 3);

        #pragma unroll
        for (int ks = 0; ks < 2; ks++) {
            uint32_t kbA = (uint32_t)(ks * 16) * 2;
            uint32_t kbB = (uint32_t)(ks * 16 * BST) * 2;

            uint32_t ah[4][4];
            #pragma unroll
            for (int mf = 0; mf < 4; mf++) {
                uint32_t off = aoffL + (uint32_t)(mf * 16 * AST) * 2 + kbA;
                LDSM_X4(ah[mf][0], ah[mf][1], ah[mf][2], ah[mf][3], aB + off);
            }
            uint32_t bh[16];
            #pragma unroll
            for (int nb = 0; nb < 4; nb++) {
                uint32_t off = boffL + (uint32_t)(nb * 16) * 2 + kbB;
                LDSM_X4_T(bh[nb * 4 + 0], bh[nb * 4 + 1], bh[nb * 4 + 2], bh[nb * 4 + 3], bB + off);
            }

            #pragma unroll
            for (int mf = 0; mf < 4; mf++)
                #pragma unroll
                for (int nf = 0; nf < 8; nf++)
                    MMA_F16(acc[mf][nf], ah[mf], bh[nf * 2], bh[nf * 2 + 1]);
        }
    }

    int rbase = m0 + wm * 64 + (lane >> 2);
    int cbase = n0 + wn * 64 + (lane & 3) * 2;
    #pragma unroll
    for (int mf = 0; mf < 4; mf++) {
        #pragma unroll
        for (int nf = 0; nf < 8; nf++) {
            int col = cbase + nf * 8;
            float b0v = bias[col], b1v = bias[col + 1];
            float v0 = acc[mf][nf][0] + b0v;
            float v1 = acc[mf][nf][1] + b1v;
            float v2 = acc[mf][nf][2] + b0v;
            float v3 = acc[mf][nf][3] + b1v;
            if (doGelu) {
                v0 = gelu_tanh(v0); v1 = gelu_tanh(v1);
                v2 = gelu_tanh(v2); v3 = gelu_tanh(v3);
            }
            int r0 = rbase + mf * 16;
            if (C) {
                *(float2*)(C + (size_t)r0 * N + col)       = make_float2(v0, v1);
                *(float2*)(C + (size_t)(r0 + 8) * N + col) = make_float2(v2, v3);
            }
            if (Ch) {
                *(uint32_t*)(Ch + (size_t)r0 * N + col)       = pack2h(v0, v1);
                *(uint32_t*)(Ch + (size_t)(r0 + 8) * N + col) = pack2h(v2, v3);
            }
        }
    }
}

// ---------------- tensor-core attention for len 64 / 128 ----------------
// smem: Qh[LEN][72] (later V), Kt[64][LEN+8], S fp32 [LEN][LEN+4], Ph[LEN][LEN+8]
template<int LEN>
__global__ __launch_bounds__(256)
void attn_mma(const __half* __restrict__ qkv, __half* __restrict__ th, int start)
{
    constexpr int QST = 72;
    constexpr int KST = LEN + 8;
    constexpr int SST = LEN + 4;
    constexpr int PST = LEN + 8;

    extern __shared__ char smraw[];
    __half* sQ  = (__half*)smraw;                 // [LEN][QST]  (later V)
    __half* sKt = sQ + LEN * QST;                 // [64][KST]
    float*  sS  = (float*)(sKt + 64 * KST);       // [LEN][SST]
    __half* sP  = (__half*)(sS + LEN * SST);      // [LEN][PST]

    int bid = blockIdx.x;
    int hh = bid & 7;
    int b  = bid >> 3;
    int tid = threadIdx.x;
    int wid = tid >> 5, lane = tid & 31;
    int h64 = hh * HD;
    size_t rowbase = (size_t)b * LTOT + start;

    uint32_t sQb = smem_u32(sQ), sKb = smem_u32(sKt);
    uint32_t sPb = smem_u32(sP);

    // load Q (contiguous) and K (transposed)
    for (int e = tid; e < LEN * 16; e += 256) {
        int l = e >> 4, c4 = (e & 15) * 4;
        size_t gi = (rowbase + l) * QKVS + h64 + c4;
        uint2 qv = *(const uint2*)(qkv + gi);
        *(uint2*)(sQ + l * QST + c4) = qv;
        __half kvv[4];
        *(uint2*)kvv = *(const uint2*)(qkv + gi + 512);
        #pragma unroll
        for (int i = 0; i < 4; i++)
            sKt[(c4 + i) * KST + l] = kvv[i];
    }
    __syncthreads();

    // ---- S = Q K^T ----
    constexpr int WMS = LEN / 32;             // warp rows groups (4 or 2)
    constexpr int CPW = LEN / (8 / WMS);      // cols per warp (64 or 16)
    constexpr int NFS = CPW / 8;              // n8 frags (8 or 2)
    constexpr int NBS = (CPW >= 16) ? CPW / 16 : 1;  // n16 ldsm blocks
    int wm_s = wid % WMS, wn_s = wid / WMS;

    float accs[2][NFS][4];
    #pragma unroll
    for (int i = 0; i < 2; i++)
        #pragma unroll
        for (int j = 0; j < NFS; j++)
            #pragma unroll
            for (int c = 0; c < 4; c++) accs[i][j][c] = 0.0f;

    uint32_t qoff = ((uint32_t)((wm_s * 32 + (lane & 15)) * QST + (lane >> 4) * 8)) * 2;
    uint32_t koff = ((uint32_t)(((lane & 7) + ((lane >> 3) & 1) * 8) * KST
                                + wn_s * CPW + (lane >> 4) * 8)) * 2;

    #pragma unroll
    for (int ks = 0; ks < 4; ks++) {
        uint32_t aq[2][4];
        #pragma unroll
        for (int mf = 0; mf < 2; mf++) {
            uint32_t off = qoff + (uint32_t)(mf * 16 * QST + ks * 16) * 2;
            LDSM_X4(aq[mf][0], aq[mf][1], aq[mf][2], aq[mf][3], sQb + off);
        }
        uint32_t bk[NFS * 2];
        #pragma unroll
        for (int nb = 0; nb < NBS; nb++) {
            uint32_t off = koff + (uint32_t)(ks * 16 * KST + nb * 16) * 2;
            LDSM_X4_T(bk[nb * 4 + 0], bk[nb * 4 + 1], bk[nb * 4 + 2], bk[nb * 4 + 3], sKb + off);
        }
        #pragma unroll
        for (int mf = 0; mf < 2; mf++)
            #pragma unroll
            for (int nf = 0; nf < NFS; nf++)
                MMA_F16(accs[mf][nf], aq[mf], bk[nf * 2], bk[nf * 2 + 1]);
    }

    // store S (scaled) to smem fp32
    {
        int r = wm_s * 32 + (lane >> 2);
        int c0 = wn_s * CPW + (lane & 3) * 2;
        #pragma unroll
        for (int mf = 0; mf < 2; mf++)
            #pragma unroll
            for (int nf = 0; nf < NFS; nf++) {
                int rr = r + mf * 16, cc = c0 + nf * 8;
                *(float2*)&sS[rr * SST + cc] =
                    make_float2(accs[mf][nf][0] * 0.125f, accs[mf][nf][1] * 0.125f);
                *(float2*)&sS[(rr + 8) * SST + cc] =
                    make_float2(accs[mf][nf][2] * 0.125f, accs[mf][nf][3] * 0.125f);
            }
    }
    __syncthreads();

    // load V into sQ (Q dead) + softmax -> Ph fp16
    for (int e = tid; e < LEN * 16; e += 256) {
        int l = e >> 4, c4 = (e & 15) * 4;
        uint2 vv = *(const uint2*)(qkv + (rowbase + l) * QKVS + h64 + c4 + 1024);
        *(uint2*)(sQ + l * QST + c4) = vv;
    }
    for (int r = tid; r < LEN; r += 256) {
        float* row = sS + r * SST;
        float mx = -1e30f;
        for (int m = 0; m < LEN; m++) mx = fmaxf(mx, row[m]);
        float sum = 0.0f;
        for (int m = 0; m < LEN; m++) {
            float ev = expf(row[m] - mx);
            row[m] = ev;
            sum += ev;
        }
        float inv = 1.0f / sum;
        __half* prow = sP + r * PST;
        for (int m = 0; m < LEN; m++)
            prow[m] = __float2half_rn(row[m] * inv);
    }
    __syncthreads();

    // ---- O = P V ----
    constexpr int WMP = LEN / 32;             // (4 or 2)
    constexpr int DPW = 8 * WMP;              // d cols per warp (32 or 16)
    constexpr int NFP = DPW / 8;              // (4 or 2)
    constexpr int NBP = (DPW >= 16) ? DPW / 16 : 1;
    constexpr int KSP = LEN / 16;             // k steps (8 or 4)
    int wm_p = wid % WMP, wn_p = wid / WMP;

    float accp[2][NFP][4];
    #pragma unroll
    for (int i = 0; i < 2; i++)
        #pragma unroll
        for (int j = 0; j < NFP; j++)
            #pragma unroll
            for (int c = 0; c < 4; c++) accp[i][j][c] = 0.0f;

    uint32_t poff = ((uint32_t)((wm_p * 32 + (lane & 15)) * PST + (lane >> 4) * 8)) * 2;
    uint32_t voff = ((uint32_t)(((lane & 7) + ((lane >> 3) & 1) * 8) * QST
                                + wn_p * DPW + (lane >> 4) * 8)) * 2;

    #pragma unroll
    for (int ks = 0; ks < KSP; ks++) {
        uint32_t ap[2][4];
        #pragma unroll
        for (int mf = 0; mf < 2; mf++) {
            uint32_t off = poff + (uint32_t)(mf * 16 * PST + ks * 16) * 2;
            LDSM_X4(ap[mf][0], ap[mf][1], ap[mf][2], ap[mf][3], sPb + off);
        }
        uint32_t bv[NFP * 2];
        #pragma unroll
        for (int nb = 0; nb < NBP; nb++) {
            uint32_t off = voff + (uint32_t)(ks * 16 * QST + nb * 16) * 2;
            LDSM_X4_T(bv[nb * 4 + 0], bv[nb * 4 + 1], bv[nb * 4 + 2], bv[nb * 4 + 3], sQb + off);
        }
        #pragma unroll
        for (int mf = 0; mf < 2; mf++)
            #pragma unroll
            for (int nf = 0; nf < NFP; nf++)
                MMA_F16(accp[mf][nf], ap[mf], bv[nf * 2], bv[nf * 2 + 1]);
    }

    {
        int r = wm_p * 32 + (lane >> 2);
        int c0 = wn_p * DPW + (lane & 3) * 2;
        #pragma unroll
        for (int mf = 0; mf < 2; mf++)
            #pragma unroll
            for (int nf = 0; nf < NFP; nf++) {
                int rr = r + mf * 16, cc = c0 + nf * 8;
                *(uint32_t*)(th + (rowbase + rr) * DM + h64 + cc) =
                    pack2h(accp[mf][nf][0], accp[mf][nf][1]);
                *(uint32_t*)(th + (rowbase + rr + 8) * DM + h64 + cc) =
                    pack2h(accp[mf][nf][2], accp[mf][nf][3]);
            }
    }
}

// ---------------- FFMA attention for len 16 / 32 (fp16 qkv input) ----------------
__global__ void attn_small(const __half* __restrict__ qkv,
                           __half* __restrict__ th,
                           int start, int len)
{
    extern __shared__ float sm[];
    int bid = blockIdx.x;
    int hh = bid & 7;
    int b  = bid >> 3;
    int tid = threadIdx.x;        // 256
    int h64 = hh * HD;
    size_t rowbase = (size_t)b * LTOT + start;
    int lenp = len + 4;

    float* sQ  = sm;                       // len*64  (later V)
    float* sKt = sm + len * HD;            // 64*(len+4)
    float* sS  = sKt + HD * lenp;          // len*(len+4)

    for (int e = tid; e < len * HD; e += 256) {
        int l = e >> 6, kk = e & 63;
        size_t gi = (rowbase + l) * QKVS + h64 + kk;
        sQ[e] = __half2float(qkv[gi]);
        sKt[kk * lenp + l] = __half2float(qkv[gi + 512]);
    }
    __syncthreads();

    int nq4 = len >> 2;
    for (int e = tid; e < len * nq4; e += 256) {
        int l  = e / nq4;
        int m4 = (e - l * nq4) * 4;
        const float* qr = sQ + l * HD;
        float ax = 0.0f, ay = 0.0f, az = 0.0f, aw = 0.0f;
        #pragma unroll 8
        for (int kk = 0; kk < HD; kk++) {
            float qv = qr[kk];
            float4 kv = *(const float4*)&sKt[kk * lenp + m4];
            ax += qv * kv.x; ay += qv * kv.y;
            az += qv * kv.z; aw += qv * kv.w;
        }
        float4 rr; rr.x = ax * 0.125f; rr.y = ay * 0.125f;
        rr.z = az * 0.125f; rr.w = aw * 0.125f;
        *(float4*)&sS[l * lenp + m4] = rr;
    }
    __syncthreads();

    for (int e = tid; e < len * HD; e += 256) {
        int l = e >> 6, kk = e & 63;
        sQ[e] = __half2float(qkv[(rowbase + l) * QKVS + h64 + kk + 1024]);
    }
    if (tid < len) {
        float* row = sS + tid * lenp;
        float mx = -1e30f;
        for (int m = 0; m < len; m++) mx = fmaxf(mx, row[m]);
        float sum = 0.0f;
        for (int m = 0; m < len; m++) {
            float ev = expf(row[m] - mx);
            row[m] = ev;
            sum += ev;
        }
        float inv = 1.0f / sum;
        for (int m = 0; m < len; m++) row[m] *= inv;
    }
    __syncthreads();

    for (int e = tid; e < len * (HD / 4); e += 256) {
        int l  = e >> 4;
        int d4 = (e & 15) * 4;
        const float* srow = sS + l * lenp;
        float ax = 0.0f, ay = 0.0f, az = 0.0f, aw = 0.0f;
        #pragma unroll 8
        for (int m = 0; m < len; m++) {
            float s = srow[m];
            float4 vv = *(const float4*)&sQ[m * HD + d4];
            ax += s * vv.x; ay += s * vv.y;
            az += s * vv.z; aw += s * vv.w;
        }
        size_t go = (rowbase + l) * DM + h64 + d4;
        *(uint2*)(th + go) = make_uint2(pack2h(ax, ay), pack2h(az, aw));
    }
}

// ---------------- residual + LayerNorm (+ optional fp16 output) ----------------
__global__ void ln_kernel(const float* __restrict__ x, const float* __restrict__ res,
                          const float* __restrict__ g, const float* __restrict__ bb,
                          float* __restrict__ out, __half* __restrict__ oh,
                          int hasRes)
{
    int row = blockIdx.x;
    int tid = threadIdx.x;   // 128
    float4 vv = ((const float4*)(x + (size_t)row * DM))[tid];
    if (hasRes) {
        float4 rr = ((const float4*)(res + (size_t)row * DM))[tid];
        vv.x += rr.x; vv.y += rr.y; vv.z += rr.z; vv.w += rr.w;
    }
    float sum = vv.x + vv.y + vv.z + vv.w;
    float sq  = vv.x * vv.x + vv.y * vv.y + vv.z * vv.z + vv.w * vv.w;

    #pragma unroll
    for (int off = 16; off; off >>= 1) {
        sum += __shfl_xor_sync(0xFFFFFFFFu, sum, off);
        sq  += __shfl_xor_sync(0xFFFFFFFFu, sq,  off);
    }
    __shared__ float red[2][4];
    int w = tid >> 5;
    if ((tid & 31) == 0) { red[0][w] = sum; red[1][w] = sq; }
    __syncthreads();
    sum = red[0][0] + red[0][1] + red[0][2] + red[0][3];
    sq  = red[1][0] + red[1][1] + red[1][2] + red[1][3];

    float mean = sum * (1.0f / DM);
    float var  = sq * (1.0f / DM) - mean * mean;
    float rstd = rsqrtf(var + 1e-5f);

    float4 gv = ((const float4*)g)[tid];
    float4 bv = ((const float4*)bb)[tid];
    float4 ov;
    ov.x = (vv.x - mean) * rstd * gv.x + bv.x;
    ov.y = (vv.y - mean) * rstd * gv.y + bv.y;
    ov.z = (vv.z - mean) * rstd * gv.z + bv.z;
    ov.w = (vv.w - mean) * rstd * gv.w + bv.w;
    ((float4*)(out + (size_t)row * DM))[tid] = ov;

    if (oh) {
        ((uint2*)(oh + (size_t)row * DM))[tid] =
            make_uint2(pack2h(ov.x, ov.y), pack2h(ov.z, ov.w));
    }
}

// ---------------- host launcher ----------------
extern "C" void kernel_launch(void* const* d_in, const int* in_sizes, int n_in,
                              void* d_out, int out_size)
{
    (void)in_sizes; (void)n_in; (void)out_size;
    const float* x_enc = (const float*)d_in[0];
    const float* W_emb = (const float*)d_in[1];
    const float* Wq    = (const float*)d_in[2];
    const float* bq    = (const float*)d_in[3];
    const float* Wk    = (const float*)d_in[4];
    const float* bk    = (const float*)d_in[5];
    const float* Wv    = (const float*)d_in[6];
    const float* bv    = (const float*)d_in[7];
    const float* Wo    = (const float*)d_in[8];
    const float* bo    = (const float*)d_in[9];
    const float* ln1_g = (const float*)d_in[10];
    const float* ln1_b = (const float*)d_in[11];
    const float* W1    = (const float*)d_in[12];
    const float* b1    = (const float*)d_in[13];
    const float* W2    = (const float*)d_in[14];
    const float* b2    = (const float*)d_in[15];
    const float* ln2_g = (const float*)d_in[16];
    const float* ln2_b = (const float*)d_in[17];
    const float* lnf_g = (const float*)d_in[18];
    const float* lnf_b = (const float*)d_in[19];

    float *h, *ob, *bqkv;
    __half *qkvh, *hh, *th, *fh, *wh;
    cudaGetSymbolAddress((void**)&h,    g_h);
    cudaGetSymbolAddress((void**)&ob,   g_o);
    cudaGetSymbolAddress((void**)&bqkv, g_bqkv);
    cudaGetSymbolAddress((void**)&qkvh, g_qkvh);
    cudaGetSymbolAddress((void**)&hh,   g_hh);
    cudaGetSymbolAddress((void**)&th,   g_th);
    cudaGetSymbolAddress((void**)&fh,   g_fh);
    cudaGetSymbolAddress((void**)&wh,   g_wh);

    cudaFuncSetAttribute(gemm_mma, cudaFuncAttributeMaxDynamicSharedMemorySize, GSMEM);
    // attn_mma smem: LEN=128 -> 138240 B ; LEN=64 -> 45056 B
    cudaFuncSetAttribute(attn_mma<128>, cudaFuncAttributeMaxDynamicSharedMemorySize, 138240);
    cudaFuncSetAttribute(attn_mma<64>,  cudaFuncAttributeMaxDynamicSharedMemorySize, 45056);

    const size_t WD = (size_t)DM * DM;
    const size_t WF = (size_t)DM * DFF;
    const size_t WQKV = (size_t)NLAYERS * 512 * QKVS;
    const size_t OO = WQKV, O1 = OO + 3 * WD, O2 = O1 + 3 * WF;

    wconv_qkv<<<(int)(WQKV / 4 + 255) / 256, 256>>>(Wq, Wk, Wv, wh);
    packbias_kernel<<<(NLAYERS * QKVS + 255) / 256, 256>>>(bq, bk, bv, bqkv);
    wconv_kernel<<<(int)(3 * WD / 4 + 255) / 256, 256>>>(Wo, wh + OO, (int)(3 * WD / 4));
    wconv_kernel<<<(int)(3 * WF / 4 + 255) / 256, 256>>>(W1, wh + O1, (int)(3 * WF / 4));
    wconv_kernel<<<(int)(3 * WF / 4 + 255) / 256, 256>>>(W2, wh + O2, (int)(3 * WF / 4));

    embed_kernel<<<dim3(LTOT, BSEQ), 256>>>(x_enc, W_emb, h, hh);

    dim3 gQKV(QKVS / 128, MROWS / 128);
    dim3 gD(DM / 128, MROWS / 128);
    dim3 gF(DFF / 128, MROWS / 128);

    for (int i = 0; i < NLAYERS; i++) {
        gemm_mma<<<gQKV, 128, GSMEM>>>(hh, wh + (size_t)i * 512 * QKVS,
                                       bqkv + i * QKVS, nullptr, qkvh,
                                       MROWS, QKVS, DM, 0);

        // seg 0: len16 @0 ; seg1: len32 @16 ; seg2: len64 @48 ; seg3: len128 @112
        {
            int len = 16, lenp = len + 4;
            size_t smem = (size_t)(len * HD + HD * lenp + len * lenp) * sizeof(float);
            attn_small<<<BSEQ * NHEADS, 256, smem>>>(qkvh, th, 0, len);
        }
        {
            int len = 32, lenp = len + 4;
            size_t smem = (size_t)(len * HD + HD * lenp + len * lenp) * sizeof(float);
            attn_small<<<BSEQ * NHEADS, 256, smem>>>(qkvh, th, 16, len);
        }
        attn_mma<64><<<BSEQ * NHEADS, 256, 45056>>>(qkvh, th, 48);
        attn_mma<128><<<BSEQ * NHEADS, 256, 138240>>>(qkvh, th, 112);

        gemm_mma<<<gD, 128, GSMEM>>>(th, wh + OO + i * WD,
                                     bo + i * DM, ob, nullptr, MROWS, DM, DM, 0);
        ln_kernel<<<MROWS, 128>>>(h, ob, ln1_g + i * DM, ln1_b + i * DM, h, hh, 1);

        gemm_mma<<<gF, 128, GSMEM>>>(hh, wh + O1 + i * WF,
                                     b1 + i * DFF, nullptr, fh, MROWS, DFF, DM, 1);
        gemm_mma<<<gD, 128, GSMEM>>>(fh, wh + O2 + i * WF,
                                     b2 + i * DM, ob, nullptr, MROWS, DM, DFF, 0);
        ln_kernel<<<MROWS, 128>>>(h, ob, ln2_g + i * DM, ln2_b + i * DM, h, hh, 1);
    }

    ln_kernel<<<MROWS, 128>>>(h, nullptr, lnf_g, lnf_b, (float*)d_out, nullptr, 0);
}